// round 14
// baseline (speedup 1.0000x reference)
#include <cuda_runtime.h>
#include <cuda_bf16.h>
#include <cstdint>

#define EPS 1e-5f
#define NGRAPH 128
#define EMAX 800000
#define NMAX 50000
#define SPLIT1 16

// ---------------- scratch (__device__ globals; no allocation allowed) -------
__device__ int g_is64_bt;
__device__ int g_nodeCnt[NMAX];
__device__ int g_nodeOff[NMAX];
__device__ int g_cursorN[NMAX];
__device__ int g_off[NGRAPH + 1];
__device__ int g_col[EMAX];
__device__ int g_row[EMAX];
__device__ int g_perm[EMAX];
__device__ int g_segS[EMAX];
__device__ int g_colS[EMAX];
__device__ int g_rowS[EMAX];
__device__ __align__(16) float g_P[NMAX * 256];
__device__ __align__(16) float g_Q[NMAX * 256];
__device__ __align__(16) uint32_t g_Pb[NMAX * 128];  // bf16x2 copy of P
__device__ __align__(16) uint32_t g_Qb[NMAX * 128];  // bf16x2 copy of Q
__device__ __align__(16) float g_h2[(size_t)EMAX * 64];
__device__ __align__(16) float g_mean1[NGRAPH * 256];
__device__ __align__(16) float g_rstd1[NGRAPH * 256];
__device__ __align__(16) float g_mean2[NGRAPH * 64];
__device__ __align__(16) float g_rstd2[NGRAPH * 64];
// accumulators: s1[32768] s2[32768] t1[8192] t2[8192]
__device__ __align__(16) float g_acc[81920];
// W2 pre-split bf16 hi/lo packed b32: [kc 8][n 64][k2 16]
__device__ __align__(16) uint32_t g_W2ph[8192];
__device__ __align__(16) uint32_t g_W2pl[8192];
// W1 pre-split bf16 hi/lo packed b32: [z 2][nb 4][kc 2][n 64][k2 16]
__device__ __align__(16) uint32_t g_W1ph[16384];
__device__ __align__(16) uint32_t g_W1pl[16384];

// ---------------- helpers ----------------------------------------------------
__device__ __forceinline__ uint32_t pkbf(float a, float b) {
    __nv_bfloat162 h = __floats2bfloat162_rn(a, b);
    return *(uint32_t*)&h;
}
__device__ __forceinline__ float2 upbf(uint32_t u) {
    __nv_bfloat162 h = *(__nv_bfloat162*)&u;
    return make_float2(__bfloat162float(h.x), __bfloat162float(h.y));
}
__device__ __forceinline__ void bsplit(float v, float& hi, float& lo) {
    __nv_bfloat16 h = __float2bfloat16(v);
    hi = __bfloat162float(h);
    lo = v - hi;
}
__device__ __forceinline__ void mma16816(float* c, uint32_t a0, uint32_t a1,
                                         uint32_t a2, uint32_t a3,
                                         uint32_t b0, uint32_t b1) {
    asm volatile(
        "mma.sync.aligned.m16n8k16.row.col.f32.bf16.bf16.f32 "
        "{%0,%1,%2,%3}, {%4,%5,%6,%7}, {%8,%9}, {%0,%1,%2,%3};"
        : "+f"(c[0]), "+f"(c[1]), "+f"(c[2]), "+f"(c[3])
        : "r"(a0), "r"(a1), "r"(a2), "r"(a3), "r"(b0), "r"(b1));
}

// ---------------- K1: prep = W split | acc zero | edge decode ----------------
__global__ void k_prep(const void* __restrict__ ei_raw,
                       const float* __restrict__ W1,
                       const float* __restrict__ W2, int E, int Nn) {
    int bid = blockIdx.x;
    int t = threadIdx.x;               // 256
    if (bid < 96) {
        int i = bid * 256 + t;
        if (i < 16384) {
            int z  = i >> 13;
            int nb = (i >> 11) & 3;
            int kc = (i >> 10) & 1;
            int n  = (i >> 4) & 63;
            int k2 = i & 15;
            int kk  = z * 64 + kc * 32 + k2 * 2;
            int col = nb * 64 + n;
            float wa = W1[kk * 256 + col];
            float wb = W1[(kk + 1) * 256 + col];
            float ha, la, hb, lb;
            bsplit(wa, ha, la); bsplit(wb, hb, lb);
            g_W1ph[i] = pkbf(ha, hb);
            g_W1pl[i] = pkbf(la, lb);
        } else {
            int j = i - 16384;
            int kc = j >> 10, n = (j >> 4) & 63, k2 = j & 15;
            int kk = kc * 32 + k2 * 2;
            float wa = W2[kk * 64 + n];
            float wb = W2[(kk + 1) * 64 + n];
            float ha, la, hb, lb;
            bsplit(wa, ha, la); bsplit(wb, hb, lb);
            g_W2ph[j] = pkbf(ha, hb);
            g_W2pl[j] = pkbf(la, lb);
        }
        return;
    }
    if (bid < 176) {                    // zero 81920 floats = 20480 float4
        int i = (bid - 96) * 256 + t;
        *(float4*)&g_acc[i * 4] = make_float4(0.f, 0.f, 0.f, 0.f);
        return;
    }
    // edge decode + node histogram
    __shared__ int s_nz;
    if (t == 0) s_nz = 0;
    __syncthreads();
    const int* ei32 = (const int*)ei_raw;
    if (ei32[2 * t + 1]) atomicOr(&s_nz, 1);
    __syncthreads();
    bool e64 = (s_nz == 0);
    int e = (bid - 176) * 256 + t;
    if (e >= E) return;
    int ci, ri;
    if (e64) {
        ci = (int)((const long long*)ei_raw)[e];
        ri = (int)((const long long*)ei_raw)[(size_t)E + e];
    } else {
        ci = ei32[e];
        ri = ei32[E + e];
    }
    ci = min(max(ci, 0), Nn - 1);
    ri = min(max(ri, 0), Nn - 1);
    g_col[e] = ci; g_row[e] = ri;
    atomicAdd(&g_nodeCnt[ci], 1);
}

// ---------------- K2: tile-scan (self-clearing) + graph offsets + bt detect ---
__global__ void k_scan_node(const void* __restrict__ bt_raw, int E, int Nn) {
    __shared__ int warpSum[32];
    __shared__ int s_bt, s_carry;
    int t = threadIdx.x;               // 1024
    int lane = t & 31, w = t >> 5;
    if (t == 0) { s_bt = 0; s_carry = 0; }
    __syncthreads();
    {
        const int* bt32 = (const int*)bt_raw;
        int lim = Nn / 2 < 16384 ? Nn / 2 : 16384;
        int nz = 0;
        for (int i = t; i < lim; i += 1024) nz |= bt32[2 * i + 1];
        for (int d = 16; d; d >>= 1) nz |= __shfl_xor_sync(~0u, nz, d);
        if (lane == 0 && nz) atomicOr(&s_bt, 1);
    }
    __syncthreads();
    bool b64 = (s_bt == 0);
    if (t == 0) g_is64_bt = b64 ? 1 : 0;

    int ntile = (Nn + 4095) >> 12;
    for (int tile = 0; tile < ntile; tile++) {
        int idx0 = (tile << 12) + t * 4;
        int c0 = 0, c1 = 0, c2 = 0, c3 = 0;
        if (idx0 + 3 < Nn) {
            int4 c = *(const int4*)&g_nodeCnt[idx0];
            c0 = c.x; c1 = c.y; c2 = c.z; c3 = c.w;
            int4 z = make_int4(0, 0, 0, 0);
            *(int4*)&g_nodeCnt[idx0] = z;
        } else {
            if (idx0 + 0 < Nn) { c0 = g_nodeCnt[idx0 + 0]; g_nodeCnt[idx0 + 0] = 0; }
            if (idx0 + 1 < Nn) { c1 = g_nodeCnt[idx0 + 1]; g_nodeCnt[idx0 + 1] = 0; }
            if (idx0 + 2 < Nn) { c2 = g_nodeCnt[idx0 + 2]; g_nodeCnt[idx0 + 2] = 0; }
            if (idx0 + 3 < Nn) { c3 = g_nodeCnt[idx0 + 3]; g_nodeCnt[idx0 + 3] = 0; }
        }
        int s = c0 + c1 + c2 + c3;
        int v = s;
        for (int d = 1; d < 32; d <<= 1) {
            int u = __shfl_up_sync(~0u, v, d);
            if (lane >= d) v += u;
        }
        if (lane == 31) warpSum[w] = v;
        __syncthreads();
        if (w == 0) {
            int x = warpSum[lane];
            for (int d = 1; d < 32; d <<= 1) {
                int u = __shfl_up_sync(~0u, x, d);
                if (lane >= d) x += u;
            }
            warpSum[lane] = x;
        }
        __syncthreads();
        int warpExcl = w ? warpSum[w - 1] : 0;
        int run = s_carry + warpExcl + (v - s);
        if (idx0 + 0 < Nn) { g_nodeOff[idx0 + 0] = run; g_cursorN[idx0 + 0] = run; run += c0; }
        if (idx0 + 1 < Nn) { g_nodeOff[idx0 + 1] = run; g_cursorN[idx0 + 1] = run; run += c1; }
        if (idx0 + 2 < Nn) { g_nodeOff[idx0 + 2] = run; g_cursorN[idx0 + 2] = run; run += c2; }
        if (idx0 + 3 < Nn) { g_nodeOff[idx0 + 3] = run; g_cursorN[idx0 + 3] = run; run += c3; }
        __syncthreads();
        if (t == 0) s_carry += warpSum[31];
        __syncthreads();
    }
    if (t < NGRAPH) {
        int lo = 0, hi = Nn;
        while (lo < hi) {
            int mid = (lo + hi) >> 1;
            long long bv = b64 ? ((const long long*)bt_raw)[mid]
                               : (long long)((const int*)bt_raw)[mid];
            if (bv < (long long)t) lo = mid + 1; else hi = mid;
        }
        g_off[t] = (lo < Nn) ? g_nodeOff[lo] : E;
    }
    if (t == 0) g_off[NGRAPH] = E;
}

// ---------------- K3: scatter (blocks 0..nS-1) + P/Q MMA (rest) --------------
__global__ void __launch_bounds__(256) k_sp(const void* __restrict__ bt_raw,
                                            const float* __restrict__ emb,
                                            int E, int Nn, int nS) {
    __shared__ uint32_t Ah[128 * 20];
    __shared__ uint32_t Al[128 * 20];
    __shared__ uint32_t Bh[64 * 20];
    __shared__ uint32_t Bl[64 * 20];
    int tid = threadIdx.x;
    if ((int)blockIdx.x < nS) {
        int e = blockIdx.x * 256 + tid;
        if (e >= E) return;
        int ci = g_col[e];
        int pos = atomicAdd(&g_cursorN[ci], 1);
        bool b64 = (g_is64_bt != 0);
        int sg = b64 ? (int)((const long long*)bt_raw)[ci]
                     : ((const int*)bt_raw)[ci];
        sg = min(max(sg, 0), NGRAPH - 1);
        g_perm[pos] = e;
        g_colS[pos] = ci;
        g_rowS[pos] = g_row[e];
        g_segS[pos] = sg;
        return;
    }
    int idx = blockIdx.x - nS;
    int m0  = (idx >> 3) * 128;
    int nb  = (idx >> 1) & 3;
    int z   = idx & 1;
    int w = tid >> 5, lane = tid & 31, gq = lane >> 2, tig = lane & 3;

    float acc[8][4];
#pragma unroll
    for (int i = 0; i < 8; i++)
#pragma unroll
        for (int j = 0; j < 4; j++) acc[i][j] = 0.f;

    int rA   = tid >> 1;
    int half = tid & 1;
    int node = min(m0 + rA, Nn - 1);
    const uint32_t* w1h = &g_W1ph[(size_t)((z * 4 + nb) * 2) * 1024];
    const uint32_t* w1l = &g_W1pl[(size_t)((z * 4 + nb) * 2) * 1024];

    for (int kc = 0; kc < 2; kc++) {
        {
            const float* er = &emb[(size_t)node * 64 + kc * 32 + half * 16];
#pragma unroll
            for (int q = 0; q < 4; q++) {
                float4 v = *(const float4*)(er + q * 4);
                float h0, l0, h1, l1, h2, l2, h3, l3;
                bsplit(v.x, h0, l0); bsplit(v.y, h1, l1);
                bsplit(v.z, h2, l2); bsplit(v.w, h3, l3);
                int o = rA * 20 + half * 8 + q * 2;
                Ah[o]     = pkbf(h0, h1);
                Ah[o + 1] = pkbf(h2, h3);
                Al[o]     = pkbf(l0, l1);
                Al[o + 1] = pkbf(l2, l3);
            }
        }
#pragma unroll
        for (int i = tid; i < 1024; i += 256) {
            int n = i >> 4, k2 = i & 15;
            Bh[n * 20 + k2] = w1h[kc * 1024 + i];
            Bl[n * 20 + k2] = w1l[kc * 1024 + i];
        }
        __syncthreads();
        int r0 = w * 16;
#pragma unroll
        for (int ks = 0; ks < 2; ks++) {
            int kb = ks * 8;
            uint32_t ah0 = Ah[(r0 + gq) * 20 + kb + tig];
            uint32_t ah1 = Ah[(r0 + gq + 8) * 20 + kb + tig];
            uint32_t ah2 = Ah[(r0 + gq) * 20 + kb + tig + 4];
            uint32_t ah3 = Ah[(r0 + gq + 8) * 20 + kb + tig + 4];
            uint32_t al0 = Al[(r0 + gq) * 20 + kb + tig];
            uint32_t al1 = Al[(r0 + gq + 8) * 20 + kb + tig];
            uint32_t al2 = Al[(r0 + gq) * 20 + kb + tig + 4];
            uint32_t al3 = Al[(r0 + gq + 8) * 20 + kb + tig + 4];
#pragma unroll
            for (int nt = 0; nt < 8; nt++) {
                int nrow = nt * 8 + gq;
                uint32_t bh0 = Bh[nrow * 20 + kb + tig];
                uint32_t bh1 = Bh[nrow * 20 + kb + tig + 4];
                uint32_t bl0 = Bl[nrow * 20 + kb + tig];
                uint32_t bl1 = Bl[nrow * 20 + kb + tig + 4];
                mma16816(acc[nt], ah0, ah1, ah2, ah3, bh0, bh1);
                mma16816(acc[nt], ah0, ah1, ah2, ah3, bl0, bl1);
                mma16816(acc[nt], al0, al1, al2, al3, bh0, bh1);
            }
        }
        __syncthreads();
    }
    float*    dst  = z ? g_Q : g_P;
    uint32_t* dstb = z ? g_Qb : g_Pb;
    int row0 = m0 + w * 16 + gq;
    int row1 = row0 + 8;
#pragma unroll
    for (int nt = 0; nt < 8; nt++) {
        int cidx = nb * 64 + nt * 8 + tig * 2;
        if (row0 < Nn) {
            *(float2*)&dst[(size_t)row0 * 256 + cidx] = make_float2(acc[nt][0], acc[nt][1]);
            dstb[(size_t)row0 * 128 + (cidx >> 1)] = pkbf(acc[nt][0], acc[nt][1]);
        }
        if (row1 < Nn) {
            *(float2*)&dst[(size_t)row1 * 256 + cidx] = make_float2(acc[nt][2], acc[nt][3]);
            dstb[(size_t)row1 * 128 + (cidx >> 1)] = pkbf(acc[nt][2], acc[nt][3]);
        }
    }
}

// ---------------- K4: stats1 accumulate (full-row uint4 gathers; profiled) ----
__global__ void k_stats1a() {
    int g    = blockIdx.x;
    int zs   = blockIdx.y;
    int lane = threadIdx.x & 31, w = threadIdx.x >> 5;
    int idx  = lane * 4;                 // u32 base within a 128-u32 row
    int start = g_off[g], end = g_off[g + 1];
    int len   = end - start;
    int chunk = (len + SPLIT1 - 1) / SPLIT1;
    int s0  = start + zs * chunk;
    int s1e = min(s0 + chunk, end);
    float s1[8], s2[8];
#pragma unroll
    for (int j = 0; j < 8; j++) { s1[j] = 0.f; s2[j] = 0.f; }
    int m = s0 + w;
    for (; m + 8 < s1e; m += 16) {
        uint4 pu0 = *(const uint4*)&g_Pb[(size_t)g_colS[m] * 128 + idx];
        uint4 qu0 = *(const uint4*)&g_Qb[(size_t)g_rowS[m] * 128 + idx];
        uint4 pu1 = *(const uint4*)&g_Pb[(size_t)g_colS[m + 8] * 128 + idx];
        uint4 qu1 = *(const uint4*)&g_Qb[(size_t)g_rowS[m + 8] * 128 + idx];
        uint32_t pw0[4] = {pu0.x, pu0.y, pu0.z, pu0.w};
        uint32_t qw0[4] = {qu0.x, qu0.y, qu0.z, qu0.w};
        uint32_t pw1[4] = {pu1.x, pu1.y, pu1.z, pu1.w};
        uint32_t qw1[4] = {qu1.x, qu1.y, qu1.z, qu1.w};
#pragma unroll
        for (int j = 0; j < 4; j++) {
            float2 p0 = upbf(pw0[j]), q0 = upbf(qw0[j]);
            float2 p1 = upbf(pw1[j]), q1 = upbf(qw1[j]);
            float va0 = p0.x + q0.x, vb0 = p0.y + q0.y;
            float va1 = p1.x + q1.x, vb1 = p1.y + q1.y;
            s1[j * 2]     += va0 + va1;
            s2[j * 2]     += va0 * va0 + va1 * va1;
            s1[j * 2 + 1] += vb0 + vb1;
            s2[j * 2 + 1] += vb0 * vb0 + vb1 * vb1;
        }
    }
    if (m < s1e) {
        uint4 pu = *(const uint4*)&g_Pb[(size_t)g_colS[m] * 128 + idx];
        uint4 qu = *(const uint4*)&g_Qb[(size_t)g_rowS[m] * 128 + idx];
        uint32_t pw[4] = {pu.x, pu.y, pu.z, pu.w};
        uint32_t qw[4] = {qu.x, qu.y, qu.z, qu.w};
#pragma unroll
        for (int j = 0; j < 4; j++) {
            float2 p = upbf(pw[j]), q = upbf(qw[j]);
            float va = p.x + q.x, vb = p.y + q.y;
            s1[j * 2]     += va;  s2[j * 2]     += va * va;
            s1[j * 2 + 1] += vb;  s2[j * 2 + 1] += vb * vb;
        }
    }
    __shared__ float r1[8][32][8], r2[8][32][8];
#pragma unroll
    for (int j = 0; j < 8; j++) { r1[w][lane][j] = s1[j]; r2[w][lane][j] = s2[j]; }
    __syncthreads();
    if (w == 0) {
#pragma unroll
        for (int t = 1; t < 8; t++)
#pragma unroll
            for (int j = 0; j < 8; j++) {
                s1[j] += r1[t][lane][j];
                s2[j] += r2[t][lane][j];
            }
        int ch = lane * 8;
#pragma unroll
        for (int j = 0; j < 8; j++) {
            atomicAdd(&g_acc[g * 256 + ch + j],         s1[j]);
            atomicAdd(&g_acc[32768 + g * 256 + ch + j], s2[j]);
        }
    }
}

// ---------------- K5: finalize mean1/rstd1 ------------------------------------
__global__ void k_fin1() {
    int g = blockIdx.x, ch = threadIdx.x;      // 128 x 256
    int cnti = g_off[g + 1] - g_off[g]; if (cnti < 1) cnti = 1;
    float inv = 1.f / (float)cnti;
    float mean = g_acc[g * 256 + ch] * inv;
    float var  = fmaxf(g_acc[32768 + g * 256 + ch] * inv - mean * mean, 0.f);
    g_mean1[g * 256 + ch] = mean;
    g_rstd1[g * 256 + ch] = rsqrtf(var + EPS);
}

// ---------------- K6: h2 MMA (round-12 mainloop) + fused stats2 epilogue -----
__global__ void __launch_bounds__(256) k_gemm2(int E) {
    __shared__ uint32_t Ah[128 * 20];
    __shared__ uint32_t Al[128 * 20];
    __shared__ uint32_t Bh[64 * 20];
    __shared__ uint32_t Bl[64 * 20];
    __shared__ int cS[128], rS[128], sS[128];
    int tid = threadIdx.x;
    int m0  = blockIdx.x * 128;
    int w = tid >> 5, lane = tid & 31, gq = lane >> 2, tig = lane & 3;
    if (tid < 128) {
        int m = m0 + tid; if (m >= E) m = E - 1;
        cS[tid] = g_colS[m]; rS[tid] = g_rowS[m]; sS[tid] = g_segS[m];
    }
    __syncthreads();

    float acc[8][4];
#pragma unroll
    for (int i = 0; i < 8; i++)
#pragma unroll
        for (int j = 0; j < 4; j++) acc[i][j] = 0.f;

    int rA   = tid >> 1;
    int half = tid & 1;
    int cA = cS[rA], rB = rS[rA], sgA = sS[rA];

    for (int kc = 0; kc < 8; kc++) {
        {
            int kb = kc * 32 + half * 16;
            const float* pB  = &g_P[(size_t)cA * 256 + kb];
            const float* qB  = &g_Q[(size_t)rB * 256 + kb];
            const float* muB = &g_mean1[sgA * 256 + kb];
            const float* rsB = &g_rstd1[sgA * 256 + kb];
#pragma unroll
            for (int q = 0; q < 4; q++) {
                float4 p  = *(const float4*)(pB + q * 4);
                float4 qv = *(const float4*)(qB + q * 4);
                float4 mu = *(const float4*)(muB + q * 4);
                float4 rs = *(const float4*)(rsB + q * 4);
                float v0 = fmaxf((p.x + qv.x - mu.x) * rs.x, 0.f);
                float v1 = fmaxf((p.y + qv.y - mu.y) * rs.y, 0.f);
                float v2 = fmaxf((p.z + qv.z - mu.z) * rs.z, 0.f);
                float v3 = fmaxf((p.w + qv.w - mu.w) * rs.w, 0.f);
                float h0, l0, h1, l1, h2, l2, h3, l3;
                bsplit(v0, h0, l0); bsplit(v1, h1, l1);
                bsplit(v2, h2, l2); bsplit(v3, h3, l3);
                int o = rA * 20 + half * 8 + q * 2;
                Ah[o]     = pkbf(h0, h1);
                Ah[o + 1] = pkbf(h2, h3);
                Al[o]     = pkbf(l0, l1);
                Al[o + 1] = pkbf(l2, l3);
            }
        }
#pragma unroll
        for (int i = tid; i < 1024; i += 256) {
            int n = i >> 4, k2 = i & 15;
            Bh[n * 20 + k2] = g_W2ph[kc * 1024 + i];
            Bl[n * 20 + k2] = g_W2pl[kc * 1024 + i];
        }
        __syncthreads();
        int r0 = w * 16;
#pragma unroll
        for (int ks = 0; ks < 2; ks++) {
            int kb = ks * 8;
            uint32_t ah0 = Ah[(r0 + gq) * 20 + kb + tig];
            uint32_t ah1 = Ah[(r0 + gq + 8) * 20 + kb + tig];
            uint32_t ah2 = Ah[(r0 + gq) * 20 + kb + tig + 4];
            uint32_t ah3 = Ah[(r0 + gq + 8) * 20 + kb + tig + 4];
            uint32_t al0 = Al[(r0 + gq) * 20 + kb + tig];
            uint32_t al1 = Al[(r0 + gq + 8) * 20 + kb + tig];
            uint32_t al2 = Al[(r0 + gq) * 20 + kb + tig + 4];
            uint32_t al3 = Al[(r0 + gq + 8) * 20 + kb + tig + 4];
#pragma unroll
            for (int nt = 0; nt < 8; nt++) {
                int nrow = nt * 8 + gq;
                uint32_t bh0 = Bh[nrow * 20 + kb + tig];
                uint32_t bh1 = Bh[nrow * 20 + kb + tig + 4];
                uint32_t bl0 = Bl[nrow * 20 + kb + tig];
                uint32_t bl1 = Bl[nrow * 20 + kb + tig + 4];
                mma16816(acc[nt], ah0, ah1, ah2, ah3, bh0, bh1);
                mma16816(acc[nt], ah0, ah1, ah2, ah3, bl0, bl1);
                mma16816(acc[nt], al0, al1, al2, al3, bh0, bh1);
            }
        }
        __syncthreads();
    }
    // ---- epilogue 1: h2 streaming stores --------------------------------------
    int row0 = m0 + w * 16 + gq;
    int row1 = row0 + 8;
#pragma unroll
    for (int nt = 0; nt < 8; nt++) {
        int cidx = nt * 8 + tig * 2;
        if (row0 < E)
            __stcs((float2*)&g_h2[(size_t)row0 * 64 + cidx],
                   make_float2(acc[nt][0], acc[nt][1]));
        if (row1 < E)
            __stcs((float2*)&g_h2[(size_t)row1 * 64 + cidx],
                   make_float2(acc[nt][2], acc[nt][3]));
    }
    // ---- epilogue 2: fused stats2 reduction ------------------------------------
    // Reuse Ah as scratch: red[0..63]=s1 per channel, red[64..127]=s2.
    float* red = (float*)Ah;
    if (tid < 128) red[tid] = 0.f;
    __syncthreads();
    bool fast = (sS[0] == sS[127]) && (m0 + 128 <= E);
    if (fast) {
        // per-thread pair sums + butterfly over gq (lane bits 2..4)
        float t1[8][2], t2[8][2];
#pragma unroll
        for (int nt = 0; nt < 8; nt++) {
            t1[nt][0] = acc[nt][0] + acc[nt][2];
            t1[nt][1] = acc[nt][1] + acc[nt][3];
            t2[nt][0] = acc[nt][0] * acc[nt][0] + acc[nt][2] * acc[nt][2];
            t2[nt][1] = acc[nt][1] * acc[nt][1] + acc[nt][3] * acc[nt][3];
        }
#pragma unroll
        for (int d = 4; d <= 16; d <<= 1) {
#pragma unroll
            for (int nt = 0; nt < 8; nt++) {
                t1[nt][0] += __shfl_xor_sync(~0u, t1[nt][0], d);
                t1[nt][1] += __shfl_xor_sync(~0u, t1[nt][1], d);
                t2[nt][0] += __shfl_xor_sync(~0u, t2[nt][0], d);
                t2[nt][1] += __shfl_xor_sync(~0u, t2[nt][1], d);
            }
        }
        if (gq == 0) {
#pragma unroll
            for (int nt = 0; nt < 8; nt++) {
                int c = nt * 8 + tig * 2;
                atomicAdd(&red[c],          t1[nt][0]);
                atomicAdd(&red[c + 1],      t1[nt][1]);
                atomicAdd(&red[64 + c],     t2[nt][0]);
                atomicAdd(&red[64 + c + 1], t2[nt][1]);
            }
        }
        __syncthreads();
        if (tid < 64) {
            int g = sS[0];
            atomicAdd(&g_acc[65536 + g * 64 + tid], red[tid]);
            atomicAdd(&g_acc[73728 + g * 64 + tid], red[tid + 64]);
        }
    } else {
        // slow path: per-row global atomics (boundary/tail blocks only)
        int sg0 = sS[w * 16 + gq];
        int sg1 = sS[w * 16 + gq + 8];
#pragma unroll
        for (int nt = 0; nt < 8; nt++) {
            int c = nt * 8 + tig * 2;
            if (row0 < E) {
                atomicAdd(&g_acc[65536 + sg0 * 64 + c],     acc[nt][0]);
                atomicAdd(&g_acc[65536 + sg0 * 64 + c + 1], acc[nt][1]);
                atomicAdd(&g_acc[73728 + sg0 * 64 + c],     acc[nt][0] * acc[nt][0]);
                atomicAdd(&g_acc[73728 + sg0 * 64 + c + 1], acc[nt][1] * acc[nt][1]);
            }
            if (row1 < E) {
                atomicAdd(&g_acc[65536 + sg1 * 64 + c],     acc[nt][2]);
                atomicAdd(&g_acc[65536 + sg1 * 64 + c + 1], acc[nt][3]);
                atomicAdd(&g_acc[73728 + sg1 * 64 + c],     acc[nt][2] * acc[nt][2]);
                atomicAdd(&g_acc[73728 + sg1 * 64 + c + 1], acc[nt][3] * acc[nt][3]);
            }
        }
    }
}

// ---------------- K7: finalize mean2/rstd2 --------------------------------------
__global__ void k_fin2() {
    int g = blockIdx.x, ch = threadIdx.x;      // 128 x 64
    int cnti = g_off[g + 1] - g_off[g]; if (cnti < 1) cnti = 1;
    float inv = 1.f / (float)cnti;
    float mean = g_acc[65536 + g * 64 + ch] * inv;
    float var  = fmaxf(g_acc[73728 + g * 64 + ch] * inv - mean * mean, 0.f);
    g_mean2[g * 64 + ch] = mean;
    g_rstd2[g * 64 + ch] = rsqrtf(var + EPS);
}

// ---------------- K8: out[perm[m]] = relu(norm2(h2)) . W3 + b3 -----------------
__global__ void k_final(const float* __restrict__ W3,
                        const float* __restrict__ b3,
                        float* __restrict__ out, int E) {
    __shared__ __align__(16) float sm[128 * 65];
    __shared__ float w3s[64];
    __shared__ int   sS[128];
    int tid = threadIdx.x;   // 128
    int m0  = blockIdx.x * 128;
    if (tid < 64) w3s[tid] = W3[tid];
    {
        int m = m0 + tid; if (m >= E) m = E - 1;
        sS[tid] = g_segS[m];
    }
    __syncthreads();
#pragma unroll
    for (int t = tid; t < 128 * 16; t += 128) {
        int rr = t >> 4, q = t & 15;
        int m = m0 + rr; if (m >= E) m = E - 1;
        float4 v  = __ldcs((const float4*)&g_h2[(size_t)m * 64 + q * 4]);
        int s = sS[rr];
        float4 mu = *(const float4*)&g_mean2[s * 64 + q * 4];
        float4 rs = *(const float4*)&g_rstd2[s * 64 + q * 4];
        float* d = &sm[rr * 65 + q * 4];
        d[0] = fmaxf((v.x - mu.x) * rs.x, 0.f);
        d[1] = fmaxf((v.y - mu.y) * rs.y, 0.f);
        d[2] = fmaxf((v.z - mu.z) * rs.z, 0.f);
        d[3] = fmaxf((v.w - mu.w) * rs.w, 0.f);
    }
    __syncthreads();
    int m = m0 + tid;
    if (m < E) {
        float acc = 0.f;
#pragma unroll
        for (int k = 0; k < 64; k++) acc += sm[tid * 65 + k] * w3s[k];
        out[g_perm[m]] = acc + b3[0];
    }
}

// ---------------- launch ---------------------------------------------------------
extern "C" void kernel_launch(void* const* d_in, const int* in_sizes, int n_in,
                              void* d_out, int out_size) {
    const float* emb = (const float*)d_in[0];
    const void*  ei  = d_in[1];
    const void*  bt  = d_in[2];
    const float* W1  = (const float*)d_in[3];
    // d_in[4] = b1 : cancels exactly through affine-free InstanceNorm
    const float* W2  = (const float*)d_in[5];
    // d_in[6] = b2 : cancels exactly through affine-free InstanceNorm
    const float* W3  = (const float*)d_in[7];
    const float* b3  = (const float*)d_in[8];
    float* out = (float*)d_out;

    int Nn = in_sizes[0] / 64;
    int E  = in_sizes[1] / 2;

    int nEdgeBlk = (E + 255) / 256;
    int nPqBlk   = ((Nn + 127) / 128) * 8;

    k_prep<<<176 + nEdgeBlk, 256>>>(ei, W1, W2, E, Nn);          // 1
    k_scan_node<<<1, 1024>>>(bt, E, Nn);                         // 2
    k_sp<<<nEdgeBlk + nPqBlk, 256>>>(bt, emb, E, Nn, nEdgeBlk);  // 3
    k_stats1a<<<dim3(128, SPLIT1), 256>>>();                     // 4 (profiled)
    k_fin1<<<128, 256>>>();                                      // 5
    k_gemm2<<<(E + 127) / 128, 256>>>(E);                        // 6 (fused stats2)
    k_fin2<<<128, 64>>>();                                       // 7
    k_final<<<(E + 127) / 128, 128>>>(W3, b3, out, E);           // 8
}

// round 15
// speedup vs baseline: 1.1137x; 1.1137x over previous
#include <cuda_runtime.h>
#include <cuda_bf16.h>
#include <cstdint>

#define EPS 1e-5f
#define NGRAPH 128
#define EMAX 800000
#define NMAX 50000
#define SPLIT1 16
#define SPLIT2 16

// ---------------- scratch (__device__ globals; no allocation allowed) -------
__device__ int g_is64_bt;
__device__ int g_nodeCnt[NMAX];
__device__ int g_nodeOff[NMAX];
__device__ int g_cursorN[NMAX];
__device__ int g_off[NGRAPH + 1];
__device__ int g_col[EMAX];
__device__ int g_row[EMAX];
__device__ int g_perm[EMAX];
__device__ int g_segS[EMAX];
__device__ int g_colS[EMAX];
__device__ int g_rowS[EMAX];
__device__ __align__(16) float g_P[NMAX * 256];
__device__ __align__(16) float g_Q[NMAX * 256];
__device__ __align__(16) uint32_t g_Pb[NMAX * 128];  // bf16x2 copy of P
__device__ __align__(16) uint32_t g_Qb[NMAX * 128];  // bf16x2 copy of Q
__device__ __align__(16) float g_h2[(size_t)EMAX * 64];
__device__ __align__(16) float g_mean1[NGRAPH * 256];
__device__ __align__(16) float g_rstd1[NGRAPH * 256];
__device__ __align__(16) float g_mean2[NGRAPH * 64];
__device__ __align__(16) float g_rstd2[NGRAPH * 64];
// accumulators: s1[32768] s2[32768] t1[8192] t2[8192]
__device__ __align__(16) float g_acc[81920];
// W2 pre-split bf16 hi/lo packed b32: [kc 8][n 64][k2 16]
__device__ __align__(16) uint32_t g_W2ph[8192];
__device__ __align__(16) uint32_t g_W2pl[8192];
// W1 pre-split bf16 hi/lo packed b32: [z 2][nb 4][kc 2][n 64][k2 16]
__device__ __align__(16) uint32_t g_W1ph[16384];
__device__ __align__(16) uint32_t g_W1pl[16384];

// ---------------- helpers ----------------------------------------------------
__device__ __forceinline__ uint32_t pkbf(float a, float b) {
    __nv_bfloat162 h = __floats2bfloat162_rn(a, b);
    return *(uint32_t*)&h;
}
__device__ __forceinline__ float2 upbf(uint32_t u) {
    __nv_bfloat162 h = *(__nv_bfloat162*)&u;
    return make_float2(__bfloat162float(h.x), __bfloat162float(h.y));
}
__device__ __forceinline__ void bsplit(float v, float& hi, float& lo) {
    __nv_bfloat16 h = __float2bfloat16(v);
    hi = __bfloat162float(h);
    lo = v - hi;
}
__device__ __forceinline__ void mma16816(float* c, uint32_t a0, uint32_t a1,
                                         uint32_t a2, uint32_t a3,
                                         uint32_t b0, uint32_t b1) {
    asm volatile(
        "mma.sync.aligned.m16n8k16.row.col.f32.bf16.bf16.f32 "
        "{%0,%1,%2,%3}, {%4,%5,%6,%7}, {%8,%9}, {%0,%1,%2,%3};"
        : "+f"(c[0]), "+f"(c[1]), "+f"(c[2]), "+f"(c[3])
        : "r"(a0), "r"(a1), "r"(a2), "r"(a3), "r"(b0), "r"(b1));
}

// ---------------- K1: prep = W split | acc zero | edge decode ----------------
__global__ void k_prep(const void* __restrict__ ei_raw,
                       const float* __restrict__ W1,
                       const float* __restrict__ W2, int E, int Nn) {
    int bid = blockIdx.x;
    int t = threadIdx.x;               // 256
    if (bid < 96) {
        int i = bid * 256 + t;
        if (i < 16384) {
            int z  = i >> 13;
            int nb = (i >> 11) & 3;
            int kc = (i >> 10) & 1;
            int n  = (i >> 4) & 63;
            int k2 = i & 15;
            int kk  = z * 64 + kc * 32 + k2 * 2;
            int col = nb * 64 + n;
            float wa = W1[kk * 256 + col];
            float wb = W1[(kk + 1) * 256 + col];
            float ha, la, hb, lb;
            bsplit(wa, ha, la); bsplit(wb, hb, lb);
            g_W1ph[i] = pkbf(ha, hb);
            g_W1pl[i] = pkbf(la, lb);
        } else {
            int j = i - 16384;
            int kc = j >> 10, n = (j >> 4) & 63, k2 = j & 15;
            int kk = kc * 32 + k2 * 2;
            float wa = W2[kk * 64 + n];
            float wb = W2[(kk + 1) * 64 + n];
            float ha, la, hb, lb;
            bsplit(wa, ha, la); bsplit(wb, hb, lb);
            g_W2ph[j] = pkbf(ha, hb);
            g_W2pl[j] = pkbf(la, lb);
        }
        return;
    }
    if (bid < 176) {                    // zero 81920 floats = 20480 float4
        int i = (bid - 96) * 256 + t;
        *(float4*)&g_acc[i * 4] = make_float4(0.f, 0.f, 0.f, 0.f);
        return;
    }
    // edge decode + node histogram
    __shared__ int s_nz;
    if (t == 0) s_nz = 0;
    __syncthreads();
    const int* ei32 = (const int*)ei_raw;
    if (ei32[2 * t + 1]) atomicOr(&s_nz, 1);
    __syncthreads();
    bool e64 = (s_nz == 0);
    int e = (bid - 176) * 256 + t;
    if (e >= E) return;
    int ci, ri;
    if (e64) {
        ci = (int)((const long long*)ei_raw)[e];
        ri = (int)((const long long*)ei_raw)[(size_t)E + e];
    } else {
        ci = ei32[e];
        ri = ei32[E + e];
    }
    ci = min(max(ci, 0), Nn - 1);
    ri = min(max(ri, 0), Nn - 1);
    g_col[e] = ci; g_row[e] = ri;
    atomicAdd(&g_nodeCnt[ci], 1);
}

// ---------------- K2: tile-scan (self-clearing) + graph offsets + bt detect ---
__global__ void k_scan_node(const void* __restrict__ bt_raw, int E, int Nn) {
    __shared__ int warpSum[32];
    __shared__ int s_bt, s_carry;
    int t = threadIdx.x;               // 1024
    int lane = t & 31, w = t >> 5;
    if (t == 0) { s_bt = 0; s_carry = 0; }
    __syncthreads();
    {
        const int* bt32 = (const int*)bt_raw;
        int lim = Nn / 2 < 16384 ? Nn / 2 : 16384;
        int nz = 0;
        for (int i = t; i < lim; i += 1024) nz |= bt32[2 * i + 1];
        for (int d = 16; d; d >>= 1) nz |= __shfl_xor_sync(~0u, nz, d);
        if (lane == 0 && nz) atomicOr(&s_bt, 1);
    }
    __syncthreads();
    bool b64 = (s_bt == 0);
    if (t == 0) g_is64_bt = b64 ? 1 : 0;

    int ntile = (Nn + 4095) >> 12;
    for (int tile = 0; tile < ntile; tile++) {
        int idx0 = (tile << 12) + t * 4;
        int c0 = 0, c1 = 0, c2 = 0, c3 = 0;
        if (idx0 + 3 < Nn) {
            int4 c = *(const int4*)&g_nodeCnt[idx0];
            c0 = c.x; c1 = c.y; c2 = c.z; c3 = c.w;
            int4 z = make_int4(0, 0, 0, 0);
            *(int4*)&g_nodeCnt[idx0] = z;
        } else {
            if (idx0 + 0 < Nn) { c0 = g_nodeCnt[idx0 + 0]; g_nodeCnt[idx0 + 0] = 0; }
            if (idx0 + 1 < Nn) { c1 = g_nodeCnt[idx0 + 1]; g_nodeCnt[idx0 + 1] = 0; }
            if (idx0 + 2 < Nn) { c2 = g_nodeCnt[idx0 + 2]; g_nodeCnt[idx0 + 2] = 0; }
            if (idx0 + 3 < Nn) { c3 = g_nodeCnt[idx0 + 3]; g_nodeCnt[idx0 + 3] = 0; }
        }
        int s = c0 + c1 + c2 + c3;
        int v = s;
        for (int d = 1; d < 32; d <<= 1) {
            int u = __shfl_up_sync(~0u, v, d);
            if (lane >= d) v += u;
        }
        if (lane == 31) warpSum[w] = v;
        __syncthreads();
        if (w == 0) {
            int x = warpSum[lane];
            for (int d = 1; d < 32; d <<= 1) {
                int u = __shfl_up_sync(~0u, x, d);
                if (lane >= d) x += u;
            }
            warpSum[lane] = x;
        }
        __syncthreads();
        int warpExcl = w ? warpSum[w - 1] : 0;
        int run = s_carry + warpExcl + (v - s);
        if (idx0 + 0 < Nn) { g_nodeOff[idx0 + 0] = run; g_cursorN[idx0 + 0] = run; run += c0; }
        if (idx0 + 1 < Nn) { g_nodeOff[idx0 + 1] = run; g_cursorN[idx0 + 1] = run; run += c1; }
        if (idx0 + 2 < Nn) { g_nodeOff[idx0 + 2] = run; g_cursorN[idx0 + 2] = run; run += c2; }
        if (idx0 + 3 < Nn) { g_nodeOff[idx0 + 3] = run; g_cursorN[idx0 + 3] = run; run += c3; }
        __syncthreads();
        if (t == 0) s_carry += warpSum[31];
        __syncthreads();
    }
    if (t < NGRAPH) {
        int lo = 0, hi = Nn;
        while (lo < hi) {
            int mid = (lo + hi) >> 1;
            long long bv = b64 ? ((const long long*)bt_raw)[mid]
                               : (long long)((const int*)bt_raw)[mid];
            if (bv < (long long)t) lo = mid + 1; else hi = mid;
        }
        g_off[t] = (lo < Nn) ? g_nodeOff[lo] : E;
    }
    if (t == 0) g_off[NGRAPH] = E;
}

// ---------------- K3: scatter (blocks 0..nS-1) + P/Q MMA (rest) --------------
__global__ void __launch_bounds__(256) k_sp(const void* __restrict__ bt_raw,
                                            const float* __restrict__ emb,
                                            int E, int Nn, int nS) {
    __shared__ uint32_t Ah[128 * 20];
    __shared__ uint32_t Al[128 * 20];
    __shared__ uint32_t Bh[64 * 20];
    __shared__ uint32_t Bl[64 * 20];
    int tid = threadIdx.x;
    if ((int)blockIdx.x < nS) {
        int e = blockIdx.x * 256 + tid;
        if (e >= E) return;
        int ci = g_col[e];
        int pos = atomicAdd(&g_cursorN[ci], 1);
        bool b64 = (g_is64_bt != 0);
        int sg = b64 ? (int)((const long long*)bt_raw)[ci]
                     : ((const int*)bt_raw)[ci];
        sg = min(max(sg, 0), NGRAPH - 1);
        g_perm[pos] = e;
        g_colS[pos] = ci;
        g_rowS[pos] = g_row[e];
        g_segS[pos] = sg;
        return;
    }
    int idx = blockIdx.x - nS;
    int m0  = (idx >> 3) * 128;
    int nb  = (idx >> 1) & 3;
    int z   = idx & 1;
    int w = tid >> 5, lane = tid & 31, gq = lane >> 2, tig = lane & 3;

    float acc[8][4];
#pragma unroll
    for (int i = 0; i < 8; i++)
#pragma unroll
        for (int j = 0; j < 4; j++) acc[i][j] = 0.f;

    int rA   = tid >> 1;
    int half = tid & 1;
    int node = min(m0 + rA, Nn - 1);
    const uint32_t* w1h = &g_W1ph[(size_t)((z * 4 + nb) * 2) * 1024];
    const uint32_t* w1l = &g_W1pl[(size_t)((z * 4 + nb) * 2) * 1024];

    for (int kc = 0; kc < 2; kc++) {
        {
            const float* er = &emb[(size_t)node * 64 + kc * 32 + half * 16];
#pragma unroll
            for (int q = 0; q < 4; q++) {
                float4 v = *(const float4*)(er + q * 4);
                float h0, l0, h1, l1, h2, l2, h3, l3;
                bsplit(v.x, h0, l0); bsplit(v.y, h1, l1);
                bsplit(v.z, h2, l2); bsplit(v.w, h3, l3);
                int o = rA * 20 + half * 8 + q * 2;
                Ah[o]     = pkbf(h0, h1);
                Ah[o + 1] = pkbf(h2, h3);
                Al[o]     = pkbf(l0, l1);
                Al[o + 1] = pkbf(l2, l3);
            }
        }
#pragma unroll
        for (int i = tid; i < 1024; i += 256) {
            int n = i >> 4, k2 = i & 15;
            Bh[n * 20 + k2] = w1h[kc * 1024 + i];
            Bl[n * 20 + k2] = w1l[kc * 1024 + i];
        }
        __syncthreads();
        int r0 = w * 16;
#pragma unroll
        for (int ks = 0; ks < 2; ks++) {
            int kb = ks * 8;
            uint32_t ah0 = Ah[(r0 + gq) * 20 + kb + tig];
            uint32_t ah1 = Ah[(r0 + gq + 8) * 20 + kb + tig];
            uint32_t ah2 = Ah[(r0 + gq) * 20 + kb + tig + 4];
            uint32_t ah3 = Ah[(r0 + gq + 8) * 20 + kb + tig + 4];
            uint32_t al0 = Al[(r0 + gq) * 20 + kb + tig];
            uint32_t al1 = Al[(r0 + gq + 8) * 20 + kb + tig];
            uint32_t al2 = Al[(r0 + gq) * 20 + kb + tig + 4];
            uint32_t al3 = Al[(r0 + gq + 8) * 20 + kb + tig + 4];
#pragma unroll
            for (int nt = 0; nt < 8; nt++) {
                int nrow = nt * 8 + gq;
                uint32_t bh0 = Bh[nrow * 20 + kb + tig];
                uint32_t bh1 = Bh[nrow * 20 + kb + tig + 4];
                uint32_t bl0 = Bl[nrow * 20 + kb + tig];
                uint32_t bl1 = Bl[nrow * 20 + kb + tig + 4];
                mma16816(acc[nt], ah0, ah1, ah2, ah3, bh0, bh1);
                mma16816(acc[nt], ah0, ah1, ah2, ah3, bl0, bl1);
                mma16816(acc[nt], al0, al1, al2, al3, bh0, bh1);
            }
        }
        __syncthreads();
    }
    float*    dst  = z ? g_Q : g_P;
    uint32_t* dstb = z ? g_Qb : g_Pb;
    int row0 = m0 + w * 16 + gq;
    int row1 = row0 + 8;
#pragma unroll
    for (int nt = 0; nt < 8; nt++) {
        int cidx = nb * 64 + nt * 8 + tig * 2;
        if (row0 < Nn) {
            *(float2*)&dst[(size_t)row0 * 256 + cidx] = make_float2(acc[nt][0], acc[nt][1]);
            dstb[(size_t)row0 * 128 + (cidx >> 1)] = pkbf(acc[nt][0], acc[nt][1]);
        }
        if (row1 < Nn) {
            *(float2*)&dst[(size_t)row1 * 256 + cidx] = make_float2(acc[nt][2], acc[nt][3]);
            dstb[(size_t)row1 * 128 + (cidx >> 1)] = pkbf(acc[nt][2], acc[nt][3]);
        }
    }
}

// ---------------- K4: stats1 accumulate (full-row uint4 gathers; profiled) ----
__global__ void k_stats1a() {
    int g    = blockIdx.x;
    int zs   = blockIdx.y;
    int lane = threadIdx.x & 31, w = threadIdx.x >> 5;
    int idx  = lane * 4;                 // u32 base within a 128-u32 row
    int start = g_off[g], end = g_off[g + 1];
    int len   = end - start;
    int chunk = (len + SPLIT1 - 1) / SPLIT1;
    int s0  = start + zs * chunk;
    int s1e = min(s0 + chunk, end);
    float s1[8], s2[8];
#pragma unroll
    for (int j = 0; j < 8; j++) { s1[j] = 0.f; s2[j] = 0.f; }
    int m = s0 + w;
    for (; m + 8 < s1e; m += 16) {
        uint4 pu0 = *(const uint4*)&g_Pb[(size_t)g_colS[m] * 128 + idx];
        uint4 qu0 = *(const uint4*)&g_Qb[(size_t)g_rowS[m] * 128 + idx];
        uint4 pu1 = *(const uint4*)&g_Pb[(size_t)g_colS[m + 8] * 128 + idx];
        uint4 qu1 = *(const uint4*)&g_Qb[(size_t)g_rowS[m + 8] * 128 + idx];
        uint32_t pw0[4] = {pu0.x, pu0.y, pu0.z, pu0.w};
        uint32_t qw0[4] = {qu0.x, qu0.y, qu0.z, qu0.w};
        uint32_t pw1[4] = {pu1.x, pu1.y, pu1.z, pu1.w};
        uint32_t qw1[4] = {qu1.x, qu1.y, qu1.z, qu1.w};
#pragma unroll
        for (int j = 0; j < 4; j++) {
            float2 p0 = upbf(pw0[j]), q0 = upbf(qw0[j]);
            float2 p1 = upbf(pw1[j]), q1 = upbf(qw1[j]);
            float va0 = p0.x + q0.x, vb0 = p0.y + q0.y;
            float va1 = p1.x + q1.x, vb1 = p1.y + q1.y;
            s1[j * 2]     += va0 + va1;
            s2[j * 2]     += va0 * va0 + va1 * va1;
            s1[j * 2 + 1] += vb0 + vb1;
            s2[j * 2 + 1] += vb0 * vb0 + vb1 * vb1;
        }
    }
    if (m < s1e) {
        uint4 pu = *(const uint4*)&g_Pb[(size_t)g_colS[m] * 128 + idx];
        uint4 qu = *(const uint4*)&g_Qb[(size_t)g_rowS[m] * 128 + idx];
        uint32_t pw[4] = {pu.x, pu.y, pu.z, pu.w};
        uint32_t qw[4] = {qu.x, qu.y, qu.z, qu.w};
#pragma unroll
        for (int j = 0; j < 4; j++) {
            float2 p = upbf(pw[j]), q = upbf(qw[j]);
            float va = p.x + q.x, vb = p.y + q.y;
            s1[j * 2]     += va;  s2[j * 2]     += va * va;
            s1[j * 2 + 1] += vb;  s2[j * 2 + 1] += vb * vb;
        }
    }
    __shared__ float r1[8][32][8], r2[8][32][8];
#pragma unroll
    for (int j = 0; j < 8; j++) { r1[w][lane][j] = s1[j]; r2[w][lane][j] = s2[j]; }
    __syncthreads();
    if (w == 0) {
#pragma unroll
        for (int t = 1; t < 8; t++)
#pragma unroll
            for (int j = 0; j < 8; j++) {
                s1[j] += r1[t][lane][j];
                s2[j] += r2[t][lane][j];
            }
        int ch = lane * 8;
#pragma unroll
        for (int j = 0; j < 8; j++) {
            atomicAdd(&g_acc[g * 256 + ch + j],         s1[j]);
            atomicAdd(&g_acc[32768 + g * 256 + ch + j], s2[j]);
        }
    }
}

// ---------------- K5: finalize mean1/rstd1 ------------------------------------
__global__ void k_fin1() {
    int g = blockIdx.x, ch = threadIdx.x;      // 128 x 256
    int cnti = g_off[g + 1] - g_off[g]; if (cnti < 1) cnti = 1;
    float inv = 1.f / (float)cnti;
    float mean = g_acc[g * 256 + ch] * inv;
    float var  = fmaxf(g_acc[32768 + g * 256 + ch] * inv - mean * mean, 0.f);
    g_mean1[g * 256 + ch] = mean;
    g_rstd1[g * 256 + ch] = rsqrtf(var + EPS);
}

// ---------------- K6: h2 via direct-load bf16 3-term MMA (round-12 mainloop,
//                  forced 4 CTAs/SM via 64-reg budget) -------------------------
__global__ void __launch_bounds__(256, 4) k_gemm2(int E) {
    __shared__ uint32_t Ah[128 * 20];
    __shared__ uint32_t Al[128 * 20];
    __shared__ uint32_t Bh[64 * 20];
    __shared__ uint32_t Bl[64 * 20];
    __shared__ int cS[128], rS[128], sS[128];
    int tid = threadIdx.x;
    int m0  = blockIdx.x * 128;
    int w = tid >> 5, lane = tid & 31, gq = lane >> 2, tig = lane & 3;
    if (tid < 128) {
        int m = m0 + tid; if (m >= E) m = E - 1;
        cS[tid] = g_colS[m]; rS[tid] = g_rowS[m]; sS[tid] = g_segS[m];
    }
    __syncthreads();

    float acc[8][4];
#pragma unroll
    for (int i = 0; i < 8; i++)
#pragma unroll
        for (int j = 0; j < 4; j++) acc[i][j] = 0.f;

    int rA   = tid >> 1;
    int half = tid & 1;
    int cA = cS[rA], rB = rS[rA], sgA = sS[rA];

    for (int kc = 0; kc < 8; kc++) {
        {
            int kb = kc * 32 + half * 16;
            const float* pB  = &g_P[(size_t)cA * 256 + kb];
            const float* qB  = &g_Q[(size_t)rB * 256 + kb];
            const float* muB = &g_mean1[sgA * 256 + kb];
            const float* rsB = &g_rstd1[sgA * 256 + kb];
#pragma unroll
            for (int q = 0; q < 4; q++) {
                float4 p  = *(const float4*)(pB + q * 4);
                float4 qv = *(const float4*)(qB + q * 4);
                float4 mu = *(const float4*)(muB + q * 4);
                float4 rs = *(const float4*)(rsB + q * 4);
                float v0 = fmaxf((p.x + qv.x - mu.x) * rs.x, 0.f);
                float v1 = fmaxf((p.y + qv.y - mu.y) * rs.y, 0.f);
                float v2 = fmaxf((p.z + qv.z - mu.z) * rs.z, 0.f);
                float v3 = fmaxf((p.w + qv.w - mu.w) * rs.w, 0.f);
                float h0, l0, h1, l1, h2, l2, h3, l3;
                bsplit(v0, h0, l0); bsplit(v1, h1, l1);
                bsplit(v2, h2, l2); bsplit(v3, h3, l3);
                int o = rA * 20 + half * 8 + q * 2;
                Ah[o]     = pkbf(h0, h1);
                Ah[o + 1] = pkbf(h2, h3);
                Al[o]     = pkbf(l0, l1);
                Al[o + 1] = pkbf(l2, l3);
            }
        }
#pragma unroll
        for (int i = tid; i < 1024; i += 256) {
            int n = i >> 4, k2 = i & 15;
            Bh[n * 20 + k2] = g_W2ph[kc * 1024 + i];
            Bl[n * 20 + k2] = g_W2pl[kc * 1024 + i];
        }
        __syncthreads();
        int r0 = w * 16;
#pragma unroll
        for (int ks = 0; ks < 2; ks++) {
            int kb = ks * 8;
            uint32_t ah0 = Ah[(r0 + gq) * 20 + kb + tig];
            uint32_t ah1 = Ah[(r0 + gq + 8) * 20 + kb + tig];
            uint32_t ah2 = Ah[(r0 + gq) * 20 + kb + tig + 4];
            uint32_t ah3 = Ah[(r0 + gq + 8) * 20 + kb + tig + 4];
            uint32_t al0 = Al[(r0 + gq) * 20 + kb + tig];
            uint32_t al1 = Al[(r0 + gq + 8) * 20 + kb + tig];
            uint32_t al2 = Al[(r0 + gq) * 20 + kb + tig + 4];
            uint32_t al3 = Al[(r0 + gq + 8) * 20 + kb + tig + 4];
#pragma unroll
            for (int nt = 0; nt < 8; nt++) {
                int nrow = nt * 8 + gq;
                uint32_t bh0 = Bh[nrow * 20 + kb + tig];
                uint32_t bh1 = Bh[nrow * 20 + kb + tig + 4];
                uint32_t bl0 = Bl[nrow * 20 + kb + tig];
                uint32_t bl1 = Bl[nrow * 20 + kb + tig + 4];
                mma16816(acc[nt], ah0, ah1, ah2, ah3, bh0, bh1);
                mma16816(acc[nt], ah0, ah1, ah2, ah3, bl0, bl1);
                mma16816(acc[nt], al0, al1, al2, al3, bh0, bh1);
            }
        }
        __syncthreads();
    }
    int row0 = m0 + w * 16 + gq;
    int row1 = row0 + 8;
#pragma unroll
    for (int nt = 0; nt < 8; nt++) {
        int cidx = nt * 8 + tig * 2;
        if (row0 < E)
            __stcs((float2*)&g_h2[(size_t)row0 * 64 + cidx],
                   make_float2(acc[nt][0], acc[nt][1]));
        if (row1 < E)
            __stcs((float2*)&g_h2[(size_t)row1 * 64 + cidx],
                   make_float2(acc[nt][2], acc[nt][3]));
    }
}

// ---------------- K7: stats2 accumulate (float2 loads, edge-split) ------------
__global__ void k_stats2a() {
    int g  = blockIdx.x;
    int zs = blockIdx.y;
    int lane = threadIdx.x & 31, w = threadIdx.x >> 5;
    int ch2 = lane * 2;
    int start = g_off[g], end = g_off[g + 1];
    int len   = end - start;
    int chunk = (len + SPLIT2 - 1) / SPLIT2;
    int s0  = start + zs * chunk;
    int s1e = min(s0 + chunk, end);
    float s1a = 0.f, s1b = 0.f, s2a = 0.f, s2b = 0.f;
    int m = s0 + w;
    for (; m + 8 < s1e; m += 16) {
        float2 v0 = *(const float2*)&g_h2[(size_t)m * 64 + ch2];
        float2 v1 = *(const float2*)&g_h2[(size_t)(m + 8) * 64 + ch2];
        s1a += v0.x + v1.x; s2a += v0.x * v0.x + v1.x * v1.x;
        s1b += v0.y + v1.y; s2b += v0.y * v0.y + v1.y * v1.y;
    }
    if (m < s1e) {
        float2 v = *(const float2*)&g_h2[(size_t)m * 64 + ch2];
        s1a += v.x; s2a += v.x * v.x;
        s1b += v.y; s2b += v.y * v.y;
    }
    __shared__ float a1[8][32][2], a2[8][32][2];
    a1[w][lane][0] = s1a; a1[w][lane][1] = s1b;
    a2[w][lane][0] = s2a; a2[w][lane][1] = s2b;
    __syncthreads();
    if (w == 0) {
#pragma unroll
        for (int t = 1; t < 8; t++) {
            s1a += a1[t][lane][0]; s1b += a1[t][lane][1];
            s2a += a2[t][lane][0]; s2b += a2[t][lane][1];
        }
        atomicAdd(&g_acc[65536 + g * 64 + ch2],     s1a);
        atomicAdd(&g_acc[65536 + g * 64 + ch2 + 1], s1b);
        atomicAdd(&g_acc[73728 + g * 64 + ch2],     s2a);
        atomicAdd(&g_acc[73728 + g * 64 + ch2 + 1], s2b);
    }
}

// ---------------- K8: finalize mean2/rstd2 --------------------------------------
__global__ void k_fin2() {
    int g = blockIdx.x, ch = threadIdx.x;      // 128 x 64
    int cnti = g_off[g + 1] - g_off[g]; if (cnti < 1) cnti = 1;
    float inv = 1.f / (float)cnti;
    float mean = g_acc[65536 + g * 64 + ch] * inv;
    float var  = fmaxf(g_acc[73728 + g * 64 + ch] * inv - mean * mean, 0.f);
    g_mean2[g * 64 + ch] = mean;
    g_rstd2[g * 64 + ch] = rsqrtf(var + EPS);
}

// ---------------- K9: out[perm[m]] = relu(norm2(h2)) . W3 + b3 -----------------
__global__ void k_final(const float* __restrict__ W3,
                        const float* __restrict__ b3,
                        float* __restrict__ out, int E) {
    __shared__ __align__(16) float sm[128 * 65];
    __shared__ float w3s[64];
    __shared__ int   sS[128];
    int tid = threadIdx.x;   // 128
    int m0  = blockIdx.x * 128;
    if (tid < 64) w3s[tid] = W3[tid];
    {
        int m = m0 + tid; if (m >= E) m = E - 1;
        sS[tid] = g_segS[m];
    }
    __syncthreads();
#pragma unroll
    for (int t = tid; t < 128 * 16; t += 128) {
        int rr = t >> 4, q = t & 15;
        int m = m0 + rr; if (m >= E) m = E - 1;
        float4 v  = __ldcs((const float4*)&g_h2[(size_t)m * 64 + q * 4]);
        int s = sS[rr];
        float4 mu = *(const float4*)&g_mean2[s * 64 + q * 4];
        float4 rs = *(const float4*)&g_rstd2[s * 64 + q * 4];
        float* d = &sm[rr * 65 + q * 4];
        d[0] = fmaxf((v.x - mu.x) * rs.x, 0.f);
        d[1] = fmaxf((v.y - mu.y) * rs.y, 0.f);
        d[2] = fmaxf((v.z - mu.z) * rs.z, 0.f);
        d[3] = fmaxf((v.w - mu.w) * rs.w, 0.f);
    }
    __syncthreads();
    int m = m0 + tid;
    if (m < E) {
        float acc = 0.f;
#pragma unroll
        for (int k = 0; k < 64; k++) acc += sm[tid * 65 + k] * w3s[k];
        out[g_perm[m]] = acc + b3[0];
    }
}

// ---------------- launch ---------------------------------------------------------
extern "C" void kernel_launch(void* const* d_in, const int* in_sizes, int n_in,
                              void* d_out, int out_size) {
    const float* emb = (const float*)d_in[0];
    const void*  ei  = d_in[1];
    const void*  bt  = d_in[2];
    const float* W1  = (const float*)d_in[3];
    // d_in[4] = b1 : cancels exactly through affine-free InstanceNorm
    const float* W2  = (const float*)d_in[5];
    // d_in[6] = b2 : cancels exactly through affine-free InstanceNorm
    const float* W3  = (const float*)d_in[7];
    const float* b3  = (const float*)d_in[8];
    float* out = (float*)d_out;

    int Nn = in_sizes[0] / 64;
    int E  = in_sizes[1] / 2;

    int nEdgeBlk = (E + 255) / 256;
    int nPqBlk   = ((Nn + 127) / 128) * 8;

    k_prep<<<176 + nEdgeBlk, 256>>>(ei, W1, W2, E, Nn);          // 1
    k_scan_node<<<1, 1024>>>(bt, E, Nn);                         // 2
    k_sp<<<nEdgeBlk + nPqBlk, 256>>>(bt, emb, E, Nn, nEdgeBlk);  // 3
    k_stats1a<<<dim3(128, SPLIT1), 256>>>();                     // 4 (profiled)
    k_fin1<<<128, 256>>>();                                      // 5
    k_gemm2<<<(E + 127) / 128, 256>>>(E);                        // 6
    k_stats2a<<<dim3(128, SPLIT2), 256>>>();                     // 7
    k_fin2<<<128, 64>>>();                                       // 8
    k_final<<<(E + 127) / 128, 128>>>(W3, b3, out, E);           // 9
}

// round 16
// speedup vs baseline: 1.1800x; 1.0596x over previous
#include <cuda_runtime.h>
#include <cuda_bf16.h>
#include <cuda_fp16.h>
#include <cstdint>

#define EPS 1e-5f
#define NGRAPH 128
#define EMAX 800000
#define NMAX 50000
#define SPLIT1 16
#define SPLIT2 16

// ---------------- scratch (__device__ globals; no allocation allowed) -------
__device__ int g_is64_bt;
__device__ int g_nodeCnt[NMAX];
__device__ int g_nodeOff[NMAX];
__device__ int g_cursorN[NMAX];
__device__ int g_off[NGRAPH + 1];
__device__ int g_col[EMAX];
__device__ int g_row[EMAX];
__device__ int g_perm[EMAX];
__device__ int g_segS[EMAX];
__device__ int g_colS[EMAX];
__device__ int g_rowS[EMAX];
__device__ __align__(16) float g_P[NMAX * 256];
__device__ __align__(16) float g_Q[NMAX * 256];
__device__ __align__(16) uint32_t g_Pb[NMAX * 128];  // bf16x2 copy of P
__device__ __align__(16) uint32_t g_Qb[NMAX * 128];  // bf16x2 copy of Q
__device__ __align__(16) uint32_t g_h2h[(size_t)EMAX * 32];  // h2 as half2
__device__ __align__(16) float g_mean1[NGRAPH * 256];
__device__ __align__(16) float g_rstd1[NGRAPH * 256];
__device__ __align__(16) float g_mean2[NGRAPH * 64];
__device__ __align__(16) float g_rstd2[NGRAPH * 64];
// accumulators: s1[32768] s2[32768] t1[8192] t2[8192]
__device__ __align__(16) float g_acc[81920];
// W2 pre-split bf16 hi/lo packed b32: [kc 8][n 64][k2 16]
__device__ __align__(16) uint32_t g_W2ph[8192];
__device__ __align__(16) uint32_t g_W2pl[8192];
// W1 pre-split bf16 hi/lo packed b32: [z 2][nb 4][kc 2][n 64][k2 16]
__device__ __align__(16) uint32_t g_W1ph[16384];
__device__ __align__(16) uint32_t g_W1pl[16384];

// ---------------- helpers ----------------------------------------------------
__device__ __forceinline__ uint32_t pkbf(float a, float b) {
    __nv_bfloat162 h = __floats2bfloat162_rn(a, b);
    return *(uint32_t*)&h;
}
__device__ __forceinline__ float2 upbf(uint32_t u) {
    __nv_bfloat162 h = *(__nv_bfloat162*)&u;
    return make_float2(__bfloat162float(h.x), __bfloat162float(h.y));
}
__device__ __forceinline__ uint32_t pkhf(float a, float b) {
    __half2 h = __floats2half2_rn(a, b);
    return *(uint32_t*)&h;
}
__device__ __forceinline__ float2 uphf(uint32_t u) {
    __half2 h = *(__half2*)&u;
    return __half22float2(h);
}
__device__ __forceinline__ void bsplit(float v, float& hi, float& lo) {
    __nv_bfloat16 h = __float2bfloat16(v);
    hi = __bfloat162float(h);
    lo = v - hi;
}
__device__ __forceinline__ void mma16816(float* c, uint32_t a0, uint32_t a1,
                                         uint32_t a2, uint32_t a3,
                                         uint32_t b0, uint32_t b1) {
    asm volatile(
        "mma.sync.aligned.m16n8k16.row.col.f32.bf16.bf16.f32 "
        "{%0,%1,%2,%3}, {%4,%5,%6,%7}, {%8,%9}, {%0,%1,%2,%3};"
        : "+f"(c[0]), "+f"(c[1]), "+f"(c[2]), "+f"(c[3])
        : "r"(a0), "r"(a1), "r"(a2), "r"(a3), "r"(b0), "r"(b1));
}

// ---------------- K1: prep = W split | acc zero | edge decode ----------------
__global__ void k_prep(const void* __restrict__ ei_raw,
                       const float* __restrict__ W1,
                       const float* __restrict__ W2, int E, int Nn) {
    int bid = blockIdx.x;
    int t = threadIdx.x;               // 256
    if (bid < 96) {
        int i = bid * 256 + t;
        if (i < 16384) {
            int z  = i >> 13;
            int nb = (i >> 11) & 3;
            int kc = (i >> 10) & 1;
            int n  = (i >> 4) & 63;
            int k2 = i & 15;
            int kk  = z * 64 + kc * 32 + k2 * 2;
            int col = nb * 64 + n;
            float wa = W1[kk * 256 + col];
            float wb = W1[(kk + 1) * 256 + col];
            float ha, la, hb, lb;
            bsplit(wa, ha, la); bsplit(wb, hb, lb);
            g_W1ph[i] = pkbf(ha, hb);
            g_W1pl[i] = pkbf(la, lb);
        } else {
            int j = i - 16384;
            int kc = j >> 10, n = (j >> 4) & 63, k2 = j & 15;
            int kk = kc * 32 + k2 * 2;
            float wa = W2[kk * 64 + n];
            float wb = W2[(kk + 1) * 64 + n];
            float ha, la, hb, lb;
            bsplit(wa, ha, la); bsplit(wb, hb, lb);
            g_W2ph[j] = pkbf(ha, hb);
            g_W2pl[j] = pkbf(la, lb);
        }
        return;
    }
    if (bid < 176) {                    // zero 81920 floats = 20480 float4
        int i = (bid - 96) * 256 + t;
        *(float4*)&g_acc[i * 4] = make_float4(0.f, 0.f, 0.f, 0.f);
        return;
    }
    // edge decode + node histogram
    __shared__ int s_nz;
    if (t == 0) s_nz = 0;
    __syncthreads();
    const int* ei32 = (const int*)ei_raw;
    if (ei32[2 * t + 1]) atomicOr(&s_nz, 1);
    __syncthreads();
    bool e64 = (s_nz == 0);
    int e = (bid - 176) * 256 + t;
    if (e >= E) return;
    int ci, ri;
    if (e64) {
        ci = (int)((const long long*)ei_raw)[e];
        ri = (int)((const long long*)ei_raw)[(size_t)E + e];
    } else {
        ci = ei32[e];
        ri = ei32[E + e];
    }
    ci = min(max(ci, 0), Nn - 1);
    ri = min(max(ri, 0), Nn - 1);
    g_col[e] = ci; g_row[e] = ri;
    atomicAdd(&g_nodeCnt[ci], 1);
}

// ---------------- K2: tile-scan (self-clearing) + graph offsets + bt detect ---
__global__ void k_scan_node(const void* __restrict__ bt_raw, int E, int Nn) {
    __shared__ int warpSum[32];
    __shared__ int s_bt, s_carry;
    int t = threadIdx.x;               // 1024
    int lane = t & 31, w = t >> 5;
    if (t == 0) { s_bt = 0; s_carry = 0; }
    __syncthreads();
    {
        const int* bt32 = (const int*)bt_raw;
        int lim = Nn / 2 < 16384 ? Nn / 2 : 16384;
        int nz = 0;
        for (int i = t; i < lim; i += 1024) nz |= bt32[2 * i + 1];
        for (int d = 16; d; d >>= 1) nz |= __shfl_xor_sync(~0u, nz, d);
        if (lane == 0 && nz) atomicOr(&s_bt, 1);
    }
    __syncthreads();
    bool b64 = (s_bt == 0);
    if (t == 0) g_is64_bt = b64 ? 1 : 0;

    int ntile = (Nn + 4095) >> 12;
    for (int tile = 0; tile < ntile; tile++) {
        int idx0 = (tile << 12) + t * 4;
        int c0 = 0, c1 = 0, c2 = 0, c3 = 0;
        if (idx0 + 3 < Nn) {
            int4 c = *(const int4*)&g_nodeCnt[idx0];
            c0 = c.x; c1 = c.y; c2 = c.z; c3 = c.w;
            int4 z = make_int4(0, 0, 0, 0);
            *(int4*)&g_nodeCnt[idx0] = z;
        } else {
            if (idx0 + 0 < Nn) { c0 = g_nodeCnt[idx0 + 0]; g_nodeCnt[idx0 + 0] = 0; }
            if (idx0 + 1 < Nn) { c1 = g_nodeCnt[idx0 + 1]; g_nodeCnt[idx0 + 1] = 0; }
            if (idx0 + 2 < Nn) { c2 = g_nodeCnt[idx0 + 2]; g_nodeCnt[idx0 + 2] = 0; }
            if (idx0 + 3 < Nn) { c3 = g_nodeCnt[idx0 + 3]; g_nodeCnt[idx0 + 3] = 0; }
        }
        int s = c0 + c1 + c2 + c3;
        int v = s;
        for (int d = 1; d < 32; d <<= 1) {
            int u = __shfl_up_sync(~0u, v, d);
            if (lane >= d) v += u;
        }
        if (lane == 31) warpSum[w] = v;
        __syncthreads();
        if (w == 0) {
            int x = warpSum[lane];
            for (int d = 1; d < 32; d <<= 1) {
                int u = __shfl_up_sync(~0u, x, d);
                if (lane >= d) x += u;
            }
            warpSum[lane] = x;
        }
        __syncthreads();
        int warpExcl = w ? warpSum[w - 1] : 0;
        int run = s_carry + warpExcl + (v - s);
        if (idx0 + 0 < Nn) { g_nodeOff[idx0 + 0] = run; g_cursorN[idx0 + 0] = run; run += c0; }
        if (idx0 + 1 < Nn) { g_nodeOff[idx0 + 1] = run; g_cursorN[idx0 + 1] = run; run += c1; }
        if (idx0 + 2 < Nn) { g_nodeOff[idx0 + 2] = run; g_cursorN[idx0 + 2] = run; run += c2; }
        if (idx0 + 3 < Nn) { g_nodeOff[idx0 + 3] = run; g_cursorN[idx0 + 3] = run; run += c3; }
        __syncthreads();
        if (t == 0) s_carry += warpSum[31];
        __syncthreads();
    }
    if (t < NGRAPH) {
        int lo = 0, hi = Nn;
        while (lo < hi) {
            int mid = (lo + hi) >> 1;
            long long bv = b64 ? ((const long long*)bt_raw)[mid]
                               : (long long)((const int*)bt_raw)[mid];
            if (bv < (long long)t) lo = mid + 1; else hi = mid;
        }
        g_off[t] = (lo < Nn) ? g_nodeOff[lo] : E;
    }
    if (t == 0) g_off[NGRAPH] = E;
}

// ---------------- K3: scatter (blocks 0..nS-1) + P/Q MMA (rest) --------------
__global__ void __launch_bounds__(256) k_sp(const void* __restrict__ bt_raw,
                                            const float* __restrict__ emb,
                                            int E, int Nn, int nS) {
    __shared__ uint32_t Ah[128 * 20];
    __shared__ uint32_t Al[128 * 20];
    __shared__ uint32_t Bh[64 * 20];
    __shared__ uint32_t Bl[64 * 20];
    int tid = threadIdx.x;
    if ((int)blockIdx.x < nS) {
        int e = blockIdx.x * 256 + tid;
        if (e >= E) return;
        int ci = g_col[e];
        int pos = atomicAdd(&g_cursorN[ci], 1);
        bool b64 = (g_is64_bt != 0);
        int sg = b64 ? (int)((const long long*)bt_raw)[ci]
                     : ((const int*)bt_raw)[ci];
        sg = min(max(sg, 0), NGRAPH - 1);
        g_perm[pos] = e;
        g_colS[pos] = ci;
        g_rowS[pos] = g_row[e];
        g_segS[pos] = sg;
        return;
    }
    int idx = blockIdx.x - nS;
    int m0  = (idx >> 3) * 128;
    int nb  = (idx >> 1) & 3;
    int z   = idx & 1;
    int w = tid >> 5, lane = tid & 31, gq = lane >> 2, tig = lane & 3;

    float acc[8][4];
#pragma unroll
    for (int i = 0; i < 8; i++)
#pragma unroll
        for (int j = 0; j < 4; j++) acc[i][j] = 0.f;

    int rA   = tid >> 1;
    int half = tid & 1;
    int node = min(m0 + rA, Nn - 1);
    const uint32_t* w1h = &g_W1ph[(size_t)((z * 4 + nb) * 2) * 1024];
    const uint32_t* w1l = &g_W1pl[(size_t)((z * 4 + nb) * 2) * 1024];

    for (int kc = 0; kc < 2; kc++) {
        {
            const float* er = &emb[(size_t)node * 64 + kc * 32 + half * 16];
#pragma unroll
            for (int q = 0; q < 4; q++) {
                float4 v = *(const float4*)(er + q * 4);
                float h0, l0, h1, l1, h2, l2, h3, l3;
                bsplit(v.x, h0, l0); bsplit(v.y, h1, l1);
                bsplit(v.z, h2, l2); bsplit(v.w, h3, l3);
                int o = rA * 20 + half * 8 + q * 2;
                Ah[o]     = pkbf(h0, h1);
                Ah[o + 1] = pkbf(h2, h3);
                Al[o]     = pkbf(l0, l1);
                Al[o + 1] = pkbf(l2, l3);
            }
        }
#pragma unroll
        for (int i = tid; i < 1024; i += 256) {
            int n = i >> 4, k2 = i & 15;
            Bh[n * 20 + k2] = w1h[kc * 1024 + i];
            Bl[n * 20 + k2] = w1l[kc * 1024 + i];
        }
        __syncthreads();
        int r0 = w * 16;
#pragma unroll
        for (int ks = 0; ks < 2; ks++) {
            int kb = ks * 8;
            uint32_t ah0 = Ah[(r0 + gq) * 20 + kb + tig];
            uint32_t ah1 = Ah[(r0 + gq + 8) * 20 + kb + tig];
            uint32_t ah2 = Ah[(r0 + gq) * 20 + kb + tig + 4];
            uint32_t ah3 = Ah[(r0 + gq + 8) * 20 + kb + tig + 4];
            uint32_t al0 = Al[(r0 + gq) * 20 + kb + tig];
            uint32_t al1 = Al[(r0 + gq + 8) * 20 + kb + tig];
            uint32_t al2 = Al[(r0 + gq) * 20 + kb + tig + 4];
            uint32_t al3 = Al[(r0 + gq + 8) * 20 + kb + tig + 4];
#pragma unroll
            for (int nt = 0; nt < 8; nt++) {
                int nrow = nt * 8 + gq;
                uint32_t bh0 = Bh[nrow * 20 + kb + tig];
                uint32_t bh1 = Bh[nrow * 20 + kb + tig + 4];
                uint32_t bl0 = Bl[nrow * 20 + kb + tig];
                uint32_t bl1 = Bl[nrow * 20 + kb + tig + 4];
                mma16816(acc[nt], ah0, ah1, ah2, ah3, bh0, bh1);
                mma16816(acc[nt], ah0, ah1, ah2, ah3, bl0, bl1);
                mma16816(acc[nt], al0, al1, al2, al3, bh0, bh1);
            }
        }
        __syncthreads();
    }
    float*    dst  = z ? g_Q : g_P;
    uint32_t* dstb = z ? g_Qb : g_Pb;
    int row0 = m0 + w * 16 + gq;
    int row1 = row0 + 8;
#pragma unroll
    for (int nt = 0; nt < 8; nt++) {
        int cidx = nb * 64 + nt * 8 + tig * 2;
        if (row0 < Nn) {
            *(float2*)&dst[(size_t)row0 * 256 + cidx] = make_float2(acc[nt][0], acc[nt][1]);
            dstb[(size_t)row0 * 128 + (cidx >> 1)] = pkbf(acc[nt][0], acc[nt][1]);
        }
        if (row1 < Nn) {
            *(float2*)&dst[(size_t)row1 * 256 + cidx] = make_float2(acc[nt][2], acc[nt][3]);
            dstb[(size_t)row1 * 128 + (cidx >> 1)] = pkbf(acc[nt][2], acc[nt][3]);
        }
    }
}

// ---------------- K4: stats1 accumulate (full-row uint4 gathers; profiled) ----
__global__ void k_stats1a() {
    int g    = blockIdx.x;
    int zs   = blockIdx.y;
    int lane = threadIdx.x & 31, w = threadIdx.x >> 5;
    int idx  = lane * 4;                 // u32 base within a 128-u32 row
    int start = g_off[g], end = g_off[g + 1];
    int len   = end - start;
    int chunk = (len + SPLIT1 - 1) / SPLIT1;
    int s0  = start + zs * chunk;
    int s1e = min(s0 + chunk, end);
    float s1[8], s2[8];
#pragma unroll
    for (int j = 0; j < 8; j++) { s1[j] = 0.f; s2[j] = 0.f; }
    int m = s0 + w;
    for (; m + 8 < s1e; m += 16) {
        uint4 pu0 = *(const uint4*)&g_Pb[(size_t)g_colS[m] * 128 + idx];
        uint4 qu0 = *(const uint4*)&g_Qb[(size_t)g_rowS[m] * 128 + idx];
        uint4 pu1 = *(const uint4*)&g_Pb[(size_t)g_colS[m + 8] * 128 + idx];
        uint4 qu1 = *(const uint4*)&g_Qb[(size_t)g_rowS[m + 8] * 128 + idx];
        uint32_t pw0[4] = {pu0.x, pu0.y, pu0.z, pu0.w};
        uint32_t qw0[4] = {qu0.x, qu0.y, qu0.z, qu0.w};
        uint32_t pw1[4] = {pu1.x, pu1.y, pu1.z, pu1.w};
        uint32_t qw1[4] = {qu1.x, qu1.y, qu1.z, qu1.w};
#pragma unroll
        for (int j = 0; j < 4; j++) {
            float2 p0 = upbf(pw0[j]), q0 = upbf(qw0[j]);
            float2 p1 = upbf(pw1[j]), q1 = upbf(qw1[j]);
            float va0 = p0.x + q0.x, vb0 = p0.y + q0.y;
            float va1 = p1.x + q1.x, vb1 = p1.y + q1.y;
            s1[j * 2]     += va0 + va1;
            s2[j * 2]     += va0 * va0 + va1 * va1;
            s1[j * 2 + 1] += vb0 + vb1;
            s2[j * 2 + 1] += vb0 * vb0 + vb1 * vb1;
        }
    }
    if (m < s1e) {
        uint4 pu = *(const uint4*)&g_Pb[(size_t)g_colS[m] * 128 + idx];
        uint4 qu = *(const uint4*)&g_Qb[(size_t)g_rowS[m] * 128 + idx];
        uint32_t pw[4] = {pu.x, pu.y, pu.z, pu.w};
        uint32_t qw[4] = {qu.x, qu.y, qu.z, qu.w};
#pragma unroll
        for (int j = 0; j < 4; j++) {
            float2 p = upbf(pw[j]), q = upbf(qw[j]);
            float va = p.x + q.x, vb = p.y + q.y;
            s1[j * 2]     += va;  s2[j * 2]     += va * va;
            s1[j * 2 + 1] += vb;  s2[j * 2 + 1] += vb * vb;
        }
    }
    __shared__ float r1[8][32][8], r2[8][32][8];
#pragma unroll
    for (int j = 0; j < 8; j++) { r1[w][lane][j] = s1[j]; r2[w][lane][j] = s2[j]; }
    __syncthreads();
    if (w == 0) {
#pragma unroll
        for (int t = 1; t < 8; t++)
#pragma unroll
            for (int j = 0; j < 8; j++) {
                s1[j] += r1[t][lane][j];
                s2[j] += r2[t][lane][j];
            }
        int ch = lane * 8;
#pragma unroll
        for (int j = 0; j < 8; j++) {
            atomicAdd(&g_acc[g * 256 + ch + j],         s1[j]);
            atomicAdd(&g_acc[32768 + g * 256 + ch + j], s2[j]);
        }
    }
}

// ---------------- K5: finalize mean1/rstd1 ------------------------------------
__global__ void k_fin1() {
    int g = blockIdx.x, ch = threadIdx.x;      // 128 x 256
    int cnti = g_off[g + 1] - g_off[g]; if (cnti < 1) cnti = 1;
    float inv = 1.f / (float)cnti;
    float mean = g_acc[g * 256 + ch] * inv;
    float var  = fmaxf(g_acc[32768 + g * 256 + ch] * inv - mean * mean, 0.f);
    g_mean1[g * 256 + ch] = mean;
    g_rstd1[g * 256 + ch] = rsqrtf(var + EPS);
}

// ---------------- K6: h2 via direct-load bf16 3-term MMA; fp16 h2 output ------
__global__ void __launch_bounds__(256) k_gemm2(int E) {
    __shared__ uint32_t Ah[128 * 20];
    __shared__ uint32_t Al[128 * 20];
    __shared__ uint32_t Bh[64 * 20];
    __shared__ uint32_t Bl[64 * 20];
    __shared__ int cS[128], rS[128], sS[128];
    int tid = threadIdx.x;
    int m0  = blockIdx.x * 128;
    int w = tid >> 5, lane = tid & 31, gq = lane >> 2, tig = lane & 3;
    if (tid < 128) {
        int m = m0 + tid; if (m >= E) m = E - 1;
        cS[tid] = g_colS[m]; rS[tid] = g_rowS[m]; sS[tid] = g_segS[m];
    }
    __syncthreads();

    float acc[8][4];
#pragma unroll
    for (int i = 0; i < 8; i++)
#pragma unroll
        for (int j = 0; j < 4; j++) acc[i][j] = 0.f;

    int rA   = tid >> 1;
    int half = tid & 1;
    int cA = cS[rA], rB = rS[rA], sgA = sS[rA];

    for (int kc = 0; kc < 8; kc++) {
        {
            int kb = kc * 32 + half * 16;
            const float* pB  = &g_P[(size_t)cA * 256 + kb];
            const float* qB  = &g_Q[(size_t)rB * 256 + kb];
            const float* muB = &g_mean1[sgA * 256 + kb];
            const float* rsB = &g_rstd1[sgA * 256 + kb];
#pragma unroll
            for (int q = 0; q < 4; q++) {
                float4 p  = *(const float4*)(pB + q * 4);
                float4 qv = *(const float4*)(qB + q * 4);
                float4 mu = *(const float4*)(muB + q * 4);
                float4 rs = *(const float4*)(rsB + q * 4);
                float v0 = fmaxf((p.x + qv.x - mu.x) * rs.x, 0.f);
                float v1 = fmaxf((p.y + qv.y - mu.y) * rs.y, 0.f);
                float v2 = fmaxf((p.z + qv.z - mu.z) * rs.z, 0.f);
                float v3 = fmaxf((p.w + qv.w - mu.w) * rs.w, 0.f);
                float h0, l0, h1, l1, h2, l2, h3, l3;
                bsplit(v0, h0, l0); bsplit(v1, h1, l1);
                bsplit(v2, h2, l2); bsplit(v3, h3, l3);
                int o = rA * 20 + half * 8 + q * 2;
                Ah[o]     = pkbf(h0, h1);
                Ah[o + 1] = pkbf(h2, h3);
                Al[o]     = pkbf(l0, l1);
                Al[o + 1] = pkbf(l2, l3);
            }
        }
#pragma unroll
        for (int i = tid; i < 1024; i += 256) {
            int n = i >> 4, k2 = i & 15;
            Bh[n * 20 + k2] = g_W2ph[kc * 1024 + i];
            Bl[n * 20 + k2] = g_W2pl[kc * 1024 + i];
        }
        __syncthreads();
        int r0 = w * 16;
#pragma unroll
        for (int ks = 0; ks < 2; ks++) {
            int kb = ks * 8;
            uint32_t ah0 = Ah[(r0 + gq) * 20 + kb + tig];
            uint32_t ah1 = Ah[(r0 + gq + 8) * 20 + kb + tig];
            uint32_t ah2 = Ah[(r0 + gq) * 20 + kb + tig + 4];
            uint32_t ah3 = Ah[(r0 + gq + 8) * 20 + kb + tig + 4];
            uint32_t al0 = Al[(r0 + gq) * 20 + kb + tig];
            uint32_t al1 = Al[(r0 + gq + 8) * 20 + kb + tig];
            uint32_t al2 = Al[(r0 + gq) * 20 + kb + tig + 4];
            uint32_t al3 = Al[(r0 + gq + 8) * 20 + kb + tig + 4];
#pragma unroll
            for (int nt = 0; nt < 8; nt++) {
                int nrow = nt * 8 + gq;
                uint32_t bh0 = Bh[nrow * 20 + kb + tig];
                uint32_t bh1 = Bh[nrow * 20 + kb + tig + 4];
                uint32_t bl0 = Bl[nrow * 20 + kb + tig];
                uint32_t bl1 = Bl[nrow * 20 + kb + tig + 4];
                mma16816(acc[nt], ah0, ah1, ah2, ah3, bh0, bh1);
                mma16816(acc[nt], ah0, ah1, ah2, ah3, bl0, bl1);
                mma16816(acc[nt], al0, al1, al2, al3, bh0, bh1);
            }
        }
        __syncthreads();
    }
    int row0 = m0 + w * 16 + gq;
    int row1 = row0 + 8;
#pragma unroll
    for (int nt = 0; nt < 8; nt++) {
        int cp = nt * 4 + tig;                      // half2 column index
        if (row0 < E)
            __stcs(&g_h2h[(size_t)row0 * 32 + cp], pkhf(acc[nt][0], acc[nt][1]));
        if (row1 < E)
            __stcs(&g_h2h[(size_t)row1 * 32 + cp], pkhf(acc[nt][2], acc[nt][3]));
    }
}

// ---------------- K7: stats2 accumulate (fp16 h2, edge-split) -----------------
__global__ void k_stats2a() {
    int g  = blockIdx.x;
    int zs = blockIdx.y;
    int lane = threadIdx.x & 31, w = threadIdx.x >> 5;
    int start = g_off[g], end = g_off[g + 1];
    int len   = end - start;
    int chunk = (len + SPLIT2 - 1) / SPLIT2;
    int s0  = start + zs * chunk;
    int s1e = min(s0 + chunk, end);
    float s1a = 0.f, s1b = 0.f, s2a = 0.f, s2b = 0.f;
    int m = s0 + w;
    for (; m + 8 < s1e; m += 16) {
        float2 v0 = uphf(g_h2h[(size_t)m * 32 + lane]);
        float2 v1 = uphf(g_h2h[(size_t)(m + 8) * 32 + lane]);
        s1a += v0.x + v1.x; s2a += v0.x * v0.x + v1.x * v1.x;
        s1b += v0.y + v1.y; s2b += v0.y * v0.y + v1.y * v1.y;
    }
    if (m < s1e) {
        float2 v = uphf(g_h2h[(size_t)m * 32 + lane]);
        s1a += v.x; s2a += v.x * v.x;
        s1b += v.y; s2b += v.y * v.y;
    }
    __shared__ float a1[8][32][2], a2[8][32][2];
    a1[w][lane][0] = s1a; a1[w][lane][1] = s1b;
    a2[w][lane][0] = s2a; a2[w][lane][1] = s2b;
    __syncthreads();
    if (w == 0) {
#pragma unroll
        for (int t = 1; t < 8; t++) {
            s1a += a1[t][lane][0]; s1b += a1[t][lane][1];
            s2a += a2[t][lane][0]; s2b += a2[t][lane][1];
        }
        int ch2 = lane * 2;
        atomicAdd(&g_acc[65536 + g * 64 + ch2],     s1a);
        atomicAdd(&g_acc[65536 + g * 64 + ch2 + 1], s1b);
        atomicAdd(&g_acc[73728 + g * 64 + ch2],     s2a);
        atomicAdd(&g_acc[73728 + g * 64 + ch2 + 1], s2b);
    }
}

// ---------------- K8: finalize mean2/rstd2 --------------------------------------
__global__ void k_fin2() {
    int g = blockIdx.x, ch = threadIdx.x;      // 128 x 64
    int cnti = g_off[g + 1] - g_off[g]; if (cnti < 1) cnti = 1;
    float inv = 1.f / (float)cnti;
    float mean = g_acc[65536 + g * 64 + ch] * inv;
    float var  = fmaxf(g_acc[73728 + g * 64 + ch] * inv - mean * mean, 0.f);
    g_mean2[g * 64 + ch] = mean;
    g_rstd2[g * 64 + ch] = rsqrtf(var + EPS);
}

// ---------------- K9: out[perm[m]] = relu(norm2(h2)) . W3 + b3 -----------------
__global__ void k_final(const float* __restrict__ W3,
                        const float* __restrict__ b3,
                        float* __restrict__ out, int E) {
    __shared__ __align__(16) float sm[128 * 65];
    __shared__ float w3s[64];
    __shared__ int   sS[128];
    int tid = threadIdx.x;   // 128
    int m0  = blockIdx.x * 128;
    if (tid < 64) w3s[tid] = W3[tid];
    {
        int m = m0 + tid; if (m >= E) m = E - 1;
        sS[tid] = g_segS[m];
    }
    __syncthreads();
#pragma unroll
    for (int t = tid; t < 128 * 8; t += 128) {
        int rr = t >> 3, q = t & 7;          // q: 4 u32 = 8 channels
        int m = m0 + rr; if (m >= E) m = E - 1;
        uint4 v4 = __ldcs((const uint4*)&g_h2h[(size_t)m * 32 + q * 4]);
        float2 va = uphf(v4.x), vb = uphf(v4.y), vc = uphf(v4.z), vd = uphf(v4.w);
        int s = sS[rr];
        float4 mu0 = *(const float4*)&g_mean2[s * 64 + q * 8];
        float4 rs0 = *(const float4*)&g_rstd2[s * 64 + q * 8];
        float4 mu1 = *(const float4*)&g_mean2[s * 64 + q * 8 + 4];
        float4 rs1 = *(const float4*)&g_rstd2[s * 64 + q * 8 + 4];
        float* d = &sm[rr * 65 + q * 8];
        d[0] = fmaxf((va.x - mu0.x) * rs0.x, 0.f);
        d[1] = fmaxf((va.y - mu0.y) * rs0.y, 0.f);
        d[2] = fmaxf((vb.x - mu0.z) * rs0.z, 0.f);
        d[3] = fmaxf((vb.y - mu0.w) * rs0.w, 0.f);
        d[4] = fmaxf((vc.x - mu1.x) * rs1.x, 0.f);
        d[5] = fmaxf((vc.y - mu1.y) * rs1.y, 0.f);
        d[6] = fmaxf((vd.x - mu1.z) * rs1.z, 0.f);
        d[7] = fmaxf((vd.y - mu1.w) * rs1.w, 0.f);
    }
    __syncthreads();
    int m = m0 + tid;
    if (m < E) {
        float acc = 0.f;
#pragma unroll
        for (int k = 0; k < 64; k++) acc += sm[tid * 65 + k] * w3s[k];
        out[g_perm[m]] = acc + b3[0];
    }
}

// ---------------- launch ---------------------------------------------------------
extern "C" void kernel_launch(void* const* d_in, const int* in_sizes, int n_in,
                              void* d_out, int out_size) {
    const float* emb = (const float*)d_in[0];
    const void*  ei  = d_in[1];
    const void*  bt  = d_in[2];
    const float* W1  = (const float*)d_in[3];
    // d_in[4] = b1 : cancels exactly through affine-free InstanceNorm
    const float* W2  = (const float*)d_in[5];
    // d_in[6] = b2 : cancels exactly through affine-free InstanceNorm
    const float* W3  = (const float*)d_in[7];
    const float* b3  = (const float*)d_in[8];
    float* out = (float*)d_out;

    int Nn = in_sizes[0] / 64;
    int E  = in_sizes[1] / 2;

    int nEdgeBlk = (E + 255) / 256;
    int nPqBlk   = ((Nn + 127) / 128) * 8;

    k_prep<<<176 + nEdgeBlk, 256>>>(ei, W1, W2, E, Nn);          // 1
    k_scan_node<<<1, 1024>>>(bt, E, Nn);                         // 2
    k_sp<<<nEdgeBlk + nPqBlk, 256>>>(bt, emb, E, Nn, nEdgeBlk);  // 3
    k_stats1a<<<dim3(128, SPLIT1), 256>>>();                     // 4 (profiled)
    k_fin1<<<128, 256>>>();                                      // 5
    k_gemm2<<<(E + 127) / 128, 256>>>(E);                        // 6
    k_stats2a<<<dim3(128, SPLIT2), 256>>>();                     // 7
    k_fin2<<<128, 64>>>();                                       // 8
    k_final<<<(E + 127) / 128, 128>>>(W3, b3, out, E);           // 9
}

// round 17
// speedup vs baseline: 1.3197x; 1.1184x over previous
#include <cuda_runtime.h>
#include <cuda_bf16.h>
#include <cuda_fp16.h>
#include <cstdint>

#define EPS 1e-5f
#define NGRAPH 128
#define EMAX 800000
#define NMAX 50000
#define SPLIT1 16
#define SPLIT2 16

// ---------------- scratch (__device__ globals; no allocation allowed) -------
__device__ int g_is64_bt;
__device__ int g_nodeCnt[NMAX];
__device__ int g_nodeOff[NMAX];
__device__ int g_cursorN[NMAX];
__device__ int g_off[NGRAPH + 1];
__device__ int g_col[EMAX];
__device__ int g_row[EMAX];
__device__ int g_perm[EMAX];
__device__ int g_segS[EMAX];
__device__ int g_colS[EMAX];
__device__ int g_rowS[EMAX];
__device__ __align__(16) uint32_t g_Ph[NMAX * 128];  // P as half2 [node][128]
__device__ __align__(16) uint32_t g_Qh[NMAX * 128];  // Q as half2
__device__ __align__(16) uint32_t g_h2h[(size_t)EMAX * 32];  // h2 as half2
__device__ __align__(16) float g_mean1[NGRAPH * 256];
__device__ __align__(16) float g_rstd1[NGRAPH * 256];
__device__ __align__(16) float g_mean2[NGRAPH * 64];
__device__ __align__(16) float g_rstd2[NGRAPH * 64];
// accumulators: s1[32768] s2[32768] t1[8192] t2[8192]
__device__ __align__(16) float g_acc[81920];
// W2 pre-split bf16 hi/lo packed b32: [kc 8][n 64][k2 16]
__device__ __align__(16) uint32_t g_W2ph[8192];
__device__ __align__(16) uint32_t g_W2pl[8192];
// W1 pre-split bf16 hi/lo packed b32: [z 2][nb 4][kc 2][n 64][k2 16]
__device__ __align__(16) uint32_t g_W1ph[16384];
__device__ __align__(16) uint32_t g_W1pl[16384];

// ---------------- helpers ----------------------------------------------------
__device__ __forceinline__ uint32_t pkbf(float a, float b) {
    __nv_bfloat162 h = __floats2bfloat162_rn(a, b);
    return *(uint32_t*)&h;
}
__device__ __forceinline__ uint32_t pkhf(float a, float b) {
    __half2 h = __floats2half2_rn(a, b);
    return *(uint32_t*)&h;
}
__device__ __forceinline__ float2 uphf(uint32_t u) {
    __half2 h = *(__half2*)&u;
    return __half22float2(h);
}
__device__ __forceinline__ void bsplit(float v, float& hi, float& lo) {
    __nv_bfloat16 h = __float2bfloat16(v);
    hi = __bfloat162float(h);
    lo = v - hi;
}
__device__ __forceinline__ void mma16816(float* c, uint32_t a0, uint32_t a1,
                                         uint32_t a2, uint32_t a3,
                                         uint32_t b0, uint32_t b1) {
    asm volatile(
        "mma.sync.aligned.m16n8k16.row.col.f32.bf16.bf16.f32 "
        "{%0,%1,%2,%3}, {%4,%5,%6,%7}, {%8,%9}, {%0,%1,%2,%3};"
        : "+f"(c[0]), "+f"(c[1]), "+f"(c[2]), "+f"(c[3])
        : "r"(a0), "r"(a1), "r"(a2), "r"(a3), "r"(b0), "r"(b1));
}

// ---------------- K1: prep = W split | acc zero | edge decode ----------------
__global__ void k_prep(const void* __restrict__ ei_raw,
                       const float* __restrict__ W1,
                       const float* __restrict__ W2, int E, int Nn) {
    int bid = blockIdx.x;
    int t = threadIdx.x;               // 256
    if (bid < 96) {
        int i = bid * 256 + t;
        if (i < 16384) {
            int z  = i >> 13;
            int nb = (i >> 11) & 3;
            int kc = (i >> 10) & 1;
            int n  = (i >> 4) & 63;
            int k2 = i & 15;
            int kk  = z * 64 + kc * 32 + k2 * 2;
            int col = nb * 64 + n;
            float wa = W1[kk * 256 + col];
            float wb = W1[(kk + 1) * 256 + col];
            float ha, la, hb, lb;
            bsplit(wa, ha, la); bsplit(wb, hb, lb);
            g_W1ph[i] = pkbf(ha, hb);
            g_W1pl[i] = pkbf(la, lb);
        } else {
            int j = i - 16384;
            int kc = j >> 10, n = (j >> 4) & 63, k2 = j & 15;
            int kk = kc * 32 + k2 * 2;
            float wa = W2[kk * 64 + n];
            float wb = W2[(kk + 1) * 64 + n];
            float ha, la, hb, lb;
            bsplit(wa, ha, la); bsplit(wb, hb, lb);
            g_W2ph[j] = pkbf(ha, hb);
            g_W2pl[j] = pkbf(la, lb);
        }
        return;
    }
    if (bid < 176) {                    // zero 81920 floats = 20480 float4
        int i = (bid - 96) * 256 + t;
        *(float4*)&g_acc[i * 4] = make_float4(0.f, 0.f, 0.f, 0.f);
        return;
    }
    // edge decode + node histogram
    __shared__ int s_nz;
    if (t == 0) s_nz = 0;
    __syncthreads();
    const int* ei32 = (const int*)ei_raw;
    if (ei32[2 * t + 1]) atomicOr(&s_nz, 1);
    __syncthreads();
    bool e64 = (s_nz == 0);
    int e = (bid - 176) * 256 + t;
    if (e >= E) return;
    int ci, ri;
    if (e64) {
        ci = (int)((const long long*)ei_raw)[e];
        ri = (int)((const long long*)ei_raw)[(size_t)E + e];
    } else {
        ci = ei32[e];
        ri = ei32[E + e];
    }
    ci = min(max(ci, 0), Nn - 1);
    ri = min(max(ri, 0), Nn - 1);
    g_col[e] = ci; g_row[e] = ri;
    atomicAdd(&g_nodeCnt[ci], 1);
}

// ---------------- K2: tile-scan (self-clearing) + graph offsets + bt detect ---
__global__ void k_scan_node(const void* __restrict__ bt_raw, int E, int Nn) {
    __shared__ int warpSum[32];
    __shared__ int s_bt, s_carry;
    int t = threadIdx.x;               // 1024
    int lane = t & 31, w = t >> 5;
    if (t == 0) { s_bt = 0; s_carry = 0; }
    __syncthreads();
    {
        const int* bt32 = (const int*)bt_raw;
        int lim = Nn / 2 < 16384 ? Nn / 2 : 16384;
        int nz = 0;
        for (int i = t; i < lim; i += 1024) nz |= bt32[2 * i + 1];
        for (int d = 16; d; d >>= 1) nz |= __shfl_xor_sync(~0u, nz, d);
        if (lane == 0 && nz) atomicOr(&s_bt, 1);
    }
    __syncthreads();
    bool b64 = (s_bt == 0);
    if (t == 0) g_is64_bt = b64 ? 1 : 0;

    int ntile = (Nn + 4095) >> 12;
    for (int tile = 0; tile < ntile; tile++) {
        int idx0 = (tile << 12) + t * 4;
        int c0 = 0, c1 = 0, c2 = 0, c3 = 0;
        if (idx0 + 3 < Nn) {
            int4 c = *(const int4*)&g_nodeCnt[idx0];
            c0 = c.x; c1 = c.y; c2 = c.z; c3 = c.w;
            int4 z = make_int4(0, 0, 0, 0);
            *(int4*)&g_nodeCnt[idx0] = z;
        } else {
            if (idx0 + 0 < Nn) { c0 = g_nodeCnt[idx0 + 0]; g_nodeCnt[idx0 + 0] = 0; }
            if (idx0 + 1 < Nn) { c1 = g_nodeCnt[idx0 + 1]; g_nodeCnt[idx0 + 1] = 0; }
            if (idx0 + 2 < Nn) { c2 = g_nodeCnt[idx0 + 2]; g_nodeCnt[idx0 + 2] = 0; }
            if (idx0 + 3 < Nn) { c3 = g_nodeCnt[idx0 + 3]; g_nodeCnt[idx0 + 3] = 0; }
        }
        int s = c0 + c1 + c2 + c3;
        int v = s;
        for (int d = 1; d < 32; d <<= 1) {
            int u = __shfl_up_sync(~0u, v, d);
            if (lane >= d) v += u;
        }
        if (lane == 31) warpSum[w] = v;
        __syncthreads();
        if (w == 0) {
            int x = warpSum[lane];
            for (int d = 1; d < 32; d <<= 1) {
                int u = __shfl_up_sync(~0u, x, d);
                if (lane >= d) x += u;
            }
            warpSum[lane] = x;
        }
        __syncthreads();
        int warpExcl = w ? warpSum[w - 1] : 0;
        int run = s_carry + warpExcl + (v - s);
        if (idx0 + 0 < Nn) { g_nodeOff[idx0 + 0] = run; g_cursorN[idx0 + 0] = run; run += c0; }
        if (idx0 + 1 < Nn) { g_nodeOff[idx0 + 1] = run; g_cursorN[idx0 + 1] = run; run += c1; }
        if (idx0 + 2 < Nn) { g_nodeOff[idx0 + 2] = run; g_cursorN[idx0 + 2] = run; run += c2; }
        if (idx0 + 3 < Nn) { g_nodeOff[idx0 + 3] = run; g_cursorN[idx0 + 3] = run; run += c3; }
        __syncthreads();
        if (t == 0) s_carry += warpSum[31];
        __syncthreads();
    }
    if (t < NGRAPH) {
        int lo = 0, hi = Nn;
        while (lo < hi) {
            int mid = (lo + hi) >> 1;
            long long bv = b64 ? ((const long long*)bt_raw)[mid]
                               : (long long)((const int*)bt_raw)[mid];
            if (bv < (long long)t) lo = mid + 1; else hi = mid;
        }
        g_off[t] = (lo < Nn) ? g_nodeOff[lo] : E;
    }
    if (t == 0) g_off[NGRAPH] = E;
}

// ---------------- K3: scatter (blocks 0..nS-1) + P/Q MMA (rest) --------------
__global__ void __launch_bounds__(256) k_sp(const void* __restrict__ bt_raw,
                                            const float* __restrict__ emb,
                                            int E, int Nn, int nS) {
    __shared__ uint32_t Ah[128 * 20];
    __shared__ uint32_t Al[128 * 20];
    __shared__ uint32_t Bh[64 * 20];
    __shared__ uint32_t Bl[64 * 20];
    int tid = threadIdx.x;
    if ((int)blockIdx.x < nS) {
        int e = blockIdx.x * 256 + tid;
        if (e >= E) return;
        int ci = g_col[e];
        int pos = atomicAdd(&g_cursorN[ci], 1);
        bool b64 = (g_is64_bt != 0);
        int sg = b64 ? (int)((const long long*)bt_raw)[ci]
                     : ((const int*)bt_raw)[ci];
        sg = min(max(sg, 0), NGRAPH - 1);
        g_perm[pos] = e;
        g_colS[pos] = ci;
        g_rowS[pos] = g_row[e];
        g_segS[pos] = sg;
        return;
    }
    int idx = blockIdx.x - nS;
    int m0  = (idx >> 3) * 128;
    int nb  = (idx >> 1) & 3;
    int z   = idx & 1;
    int w = tid >> 5, lane = tid & 31, gq = lane >> 2, tig = lane & 3;

    float acc[8][4];
#pragma unroll
    for (int i = 0; i < 8; i++)
#pragma unroll
        for (int j = 0; j < 4; j++) acc[i][j] = 0.f;

    int rA   = tid >> 1;
    int half = tid & 1;
    int node = min(m0 + rA, Nn - 1);
    const uint32_t* w1h = &g_W1ph[(size_t)((z * 4 + nb) * 2) * 1024];
    const uint32_t* w1l = &g_W1pl[(size_t)((z * 4 + nb) * 2) * 1024];

    for (int kc = 0; kc < 2; kc++) {
        {
            const float* er = &emb[(size_t)node * 64 + kc * 32 + half * 16];
#pragma unroll
            for (int q = 0; q < 4; q++) {
                float4 v = *(const float4*)(er + q * 4);
                float h0, l0, h1, l1, h2, l2, h3, l3;
                bsplit(v.x, h0, l0); bsplit(v.y, h1, l1);
                bsplit(v.z, h2, l2); bsplit(v.w, h3, l3);
                int o = rA * 20 + half * 8 + q * 2;
                Ah[o]     = pkbf(h0, h1);
                Ah[o + 1] = pkbf(h2, h3);
                Al[o]     = pkbf(l0, l1);
                Al[o + 1] = pkbf(l2, l3);
            }
        }
#pragma unroll
        for (int i = tid; i < 1024; i += 256) {
            int n = i >> 4, k2 = i & 15;
            Bh[n * 20 + k2] = w1h[kc * 1024 + i];
            Bl[n * 20 + k2] = w1l[kc * 1024 + i];
        }
        __syncthreads();
        int r0 = w * 16;
#pragma unroll
        for (int ks = 0; ks < 2; ks++) {
            int kb = ks * 8;
            uint32_t ah0 = Ah[(r0 + gq) * 20 + kb + tig];
            uint32_t ah1 = Ah[(r0 + gq + 8) * 20 + kb + tig];
            uint32_t ah2 = Ah[(r0 + gq) * 20 + kb + tig + 4];
            uint32_t ah3 = Ah[(r0 + gq + 8) * 20 + kb + tig + 4];
            uint32_t al0 = Al[(r0 + gq) * 20 + kb + tig];
            uint32_t al1 = Al[(r0 + gq + 8) * 20 + kb + tig];
            uint32_t al2 = Al[(r0 + gq) * 20 + kb + tig + 4];
            uint32_t al3 = Al[(r0 + gq + 8) * 20 + kb + tig + 4];
#pragma unroll
            for (int nt = 0; nt < 8; nt++) {
                int nrow = nt * 8 + gq;
                uint32_t bh0 = Bh[nrow * 20 + kb + tig];
                uint32_t bh1 = Bh[nrow * 20 + kb + tig + 4];
                uint32_t bl0 = Bl[nrow * 20 + kb + tig];
                uint32_t bl1 = Bl[nrow * 20 + kb + tig + 4];
                mma16816(acc[nt], ah0, ah1, ah2, ah3, bh0, bh1);
                mma16816(acc[nt], ah0, ah1, ah2, ah3, bl0, bl1);
                mma16816(acc[nt], al0, al1, al2, al3, bh0, bh1);
            }
        }
        __syncthreads();
    }
    uint32_t* dsth = z ? g_Qh : g_Ph;
    int row0 = m0 + w * 16 + gq;
    int row1 = row0 + 8;
#pragma unroll
    for (int nt = 0; nt < 8; nt++) {
        int cp = nb * 32 + nt * 4 + tig;          // half2 column index
        if (row0 < Nn)
            dsth[(size_t)row0 * 128 + cp] = pkhf(acc[nt][0], acc[nt][1]);
        if (row1 < Nn)
            dsth[(size_t)row1 * 128 + cp] = pkhf(acc[nt][2], acc[nt][3]);
    }
}

// ---------------- K4: stats1 accumulate (fp16 full-row uint4; profiled) -------
__global__ void k_stats1a() {
    int g    = blockIdx.x;
    int zs   = blockIdx.y;
    int lane = threadIdx.x & 31, w = threadIdx.x >> 5;
    int idx  = lane * 4;                 // u32 base within a 128-u32 row
    int start = g_off[g], end = g_off[g + 1];
    int len   = end - start;
    int chunk = (len + SPLIT1 - 1) / SPLIT1;
    int s0  = start + zs * chunk;
    int s1e = min(s0 + chunk, end);
    float s1[8], s2[8];
#pragma unroll
    for (int j = 0; j < 8; j++) { s1[j] = 0.f; s2[j] = 0.f; }
    int m = s0 + w;
    for (; m + 8 < s1e; m += 16) {
        uint4 pu0 = *(const uint4*)&g_Ph[(size_t)g_colS[m] * 128 + idx];
        uint4 qu0 = *(const uint4*)&g_Qh[(size_t)g_rowS[m] * 128 + idx];
        uint4 pu1 = *(const uint4*)&g_Ph[(size_t)g_colS[m + 8] * 128 + idx];
        uint4 qu1 = *(const uint4*)&g_Qh[(size_t)g_rowS[m + 8] * 128 + idx];
        uint32_t pw0[4] = {pu0.x, pu0.y, pu0.z, pu0.w};
        uint32_t qw0[4] = {qu0.x, qu0.y, qu0.z, qu0.w};
        uint32_t pw1[4] = {pu1.x, pu1.y, pu1.z, pu1.w};
        uint32_t qw1[4] = {qu1.x, qu1.y, qu1.z, qu1.w};
#pragma unroll
        for (int j = 0; j < 4; j++) {
            float2 p0 = uphf(pw0[j]), q0 = uphf(qw0[j]);
            float2 p1 = uphf(pw1[j]), q1 = uphf(qw1[j]);
            float va0 = p0.x + q0.x, vb0 = p0.y + q0.y;
            float va1 = p1.x + q1.x, vb1 = p1.y + q1.y;
            s1[j * 2]     += va0 + va1;
            s2[j * 2]     += va0 * va0 + va1 * va1;
            s1[j * 2 + 1] += vb0 + vb1;
            s2[j * 2 + 1] += vb0 * vb0 + vb1 * vb1;
        }
    }
    if (m < s1e) {
        uint4 pu = *(const uint4*)&g_Ph[(size_t)g_colS[m] * 128 + idx];
        uint4 qu = *(const uint4*)&g_Qh[(size_t)g_rowS[m] * 128 + idx];
        uint32_t pw[4] = {pu.x, pu.y, pu.z, pu.w};
        uint32_t qw[4] = {qu.x, qu.y, qu.z, qu.w};
#pragma unroll
        for (int j = 0; j < 4; j++) {
            float2 p = uphf(pw[j]), q = uphf(qw[j]);
            float va = p.x + q.x, vb = p.y + q.y;
            s1[j * 2]     += va;  s2[j * 2]     += va * va;
            s1[j * 2 + 1] += vb;  s2[j * 2 + 1] += vb * vb;
        }
    }
    __shared__ float r1[8][32][8], r2[8][32][8];
#pragma unroll
    for (int j = 0; j < 8; j++) { r1[w][lane][j] = s1[j]; r2[w][lane][j] = s2[j]; }
    __syncthreads();
    if (w == 0) {
#pragma unroll
        for (int t = 1; t < 8; t++)
#pragma unroll
            for (int j = 0; j < 8; j++) {
                s1[j] += r1[t][lane][j];
                s2[j] += r2[t][lane][j];
            }
        int ch = lane * 8;
#pragma unroll
        for (int j = 0; j < 8; j++) {
            atomicAdd(&g_acc[g * 256 + ch + j],         s1[j]);
            atomicAdd(&g_acc[32768 + g * 256 + ch + j], s2[j]);
        }
    }
}

// ---------------- K5: finalize mean1/rstd1 ------------------------------------
__global__ void k_fin1() {
    int g = blockIdx.x, ch = threadIdx.x;      // 128 x 256
    int cnti = g_off[g + 1] - g_off[g]; if (cnti < 1) cnti = 1;
    float inv = 1.f / (float)cnti;
    float mean = g_acc[g * 256 + ch] * inv;
    float var  = fmaxf(g_acc[32768 + g * 256 + ch] * inv - mean * mean, 0.f);
    g_mean1[g * 256 + ch] = mean;
    g_rstd1[g * 256 + ch] = rsqrtf(var + EPS);
}

// ---------------- K6: h2 via bf16 3-term MMA; fp16 P/Q in, fp16 h2 out --------
__global__ void __launch_bounds__(256) k_gemm2(int E) {
    __shared__ uint32_t Ah[128 * 20];
    __shared__ uint32_t Al[128 * 20];
    __shared__ uint32_t Bh[64 * 20];
    __shared__ uint32_t Bl[64 * 20];
    __shared__ int cS[128], rS[128], sS[128];
    int tid = threadIdx.x;
    int m0  = blockIdx.x * 128;
    int w = tid >> 5, lane = tid & 31, gq = lane >> 2, tig = lane & 3;
    if (tid < 128) {
        int m = m0 + tid; if (m >= E) m = E - 1;
        cS[tid] = g_colS[m]; rS[tid] = g_rowS[m]; sS[tid] = g_segS[m];
    }
    __syncthreads();

    float acc[8][4];
#pragma unroll
    for (int i = 0; i < 8; i++)
#pragma unroll
        for (int j = 0; j < 4; j++) acc[i][j] = 0.f;

    int rA   = tid >> 1;
    int half = tid & 1;
    int cA = cS[rA], rB = rS[rA], sgA = sS[rA];

    for (int kc = 0; kc < 8; kc++) {
        {
            int kb = kc * 32 + half * 16;     // channel base (16 channels)
            int ub = kb >> 1;                  // u32 base
            uint4 pu0 = *(const uint4*)&g_Ph[(size_t)cA * 128 + ub];
            uint4 pu1 = *(const uint4*)&g_Ph[(size_t)cA * 128 + ub + 4];
            uint4 qu0 = *(const uint4*)&g_Qh[(size_t)rB * 128 + ub];
            uint4 qu1 = *(const uint4*)&g_Qh[(size_t)rB * 128 + ub + 4];
            uint32_t pw[8] = {pu0.x, pu0.y, pu0.z, pu0.w,
                              pu1.x, pu1.y, pu1.z, pu1.w};
            uint32_t qw[8] = {qu0.x, qu0.y, qu0.z, qu0.w,
                              qu1.x, qu1.y, qu1.z, qu1.w};
            const float* muB = &g_mean1[sgA * 256 + kb];
            const float* rsB = &g_rstd1[sgA * 256 + kb];
#pragma unroll
            for (int q = 0; q < 4; q++) {
                float2 pA = uphf(pw[2 * q]),     pBv = uphf(pw[2 * q + 1]);
                float2 qA = uphf(qw[2 * q]),     qBv = uphf(qw[2 * q + 1]);
                float4 mu = *(const float4*)(muB + q * 4);
                float4 rs = *(const float4*)(rsB + q * 4);
                float v0 = fmaxf((pA.x + qA.x - mu.x) * rs.x, 0.f);
                float v1 = fmaxf((pA.y + qA.y - mu.y) * rs.y, 0.f);
                float v2 = fmaxf((pBv.x + qBv.x - mu.z) * rs.z, 0.f);
                float v3 = fmaxf((pBv.y + qBv.y - mu.w) * rs.w, 0.f);
                float h0, l0, h1, l1, h2, l2, h3, l3;
                bsplit(v0, h0, l0); bsplit(v1, h1, l1);
                bsplit(v2, h2, l2); bsplit(v3, h3, l3);
                int o = rA * 20 + half * 8 + q * 2;
                Ah[o]     = pkbf(h0, h1);
                Ah[o + 1] = pkbf(h2, h3);
                Al[o]     = pkbf(l0, l1);
                Al[o + 1] = pkbf(l2, l3);
            }
        }
#pragma unroll
        for (int i = tid; i < 1024; i += 256) {
            int n = i >> 4, k2 = i & 15;
            Bh[n * 20 + k2] = g_W2ph[kc * 1024 + i];
            Bl[n * 20 + k2] = g_W2pl[kc * 1024 + i];
        }
        __syncthreads();
        int r0 = w * 16;
#pragma unroll
        for (int ks = 0; ks < 2; ks++) {
            int kb = ks * 8;
            uint32_t ah0 = Ah[(r0 + gq) * 20 + kb + tig];
            uint32_t ah1 = Ah[(r0 + gq + 8) * 20 + kb + tig];
            uint32_t ah2 = Ah[(r0 + gq) * 20 + kb + tig + 4];
            uint32_t ah3 = Ah[(r0 + gq + 8) * 20 + kb + tig + 4];
            uint32_t al0 = Al[(r0 + gq) * 20 + kb + tig];
            uint32_t al1 = Al[(r0 + gq + 8) * 20 + kb + tig];
            uint32_t al2 = Al[(r0 + gq) * 20 + kb + tig + 4];
            uint32_t al3 = Al[(r0 + gq + 8) * 20 + kb + tig + 4];
#pragma unroll
            for (int nt = 0; nt < 8; nt++) {
                int nrow = nt * 8 + gq;
                uint32_t bh0 = Bh[nrow * 20 + kb + tig];
                uint32_t bh1 = Bh[nrow * 20 + kb + tig + 4];
                uint32_t bl0 = Bl[nrow * 20 + kb + tig];
                uint32_t bl1 = Bl[nrow * 20 + kb + tig + 4];
                mma16816(acc[nt], ah0, ah1, ah2, ah3, bh0, bh1);
                mma16816(acc[nt], ah0, ah1, ah2, ah3, bl0, bl1);
                mma16816(acc[nt], al0, al1, al2, al3, bh0, bh1);
            }
        }
        __syncthreads();
    }
    int row0 = m0 + w * 16 + gq;
    int row1 = row0 + 8;
#pragma unroll
    for (int nt = 0; nt < 8; nt++) {
        int cp = nt * 4 + tig;                      // half2 column index
        if (row0 < E)
            __stcs(&g_h2h[(size_t)row0 * 32 + cp], pkhf(acc[nt][0], acc[nt][1]));
        if (row1 < E)
            __stcs(&g_h2h[(size_t)row1 * 32 + cp], pkhf(acc[nt][2], acc[nt][3]));
    }
}

// ---------------- K7: stats2 accumulate (fp16 h2, edge-split) -----------------
__global__ void k_stats2a() {
    int g  = blockIdx.x;
    int zs = blockIdx.y;
    int lane = threadIdx.x & 31, w = threadIdx.x >> 5;
    int start = g_off[g], end = g_off[g + 1];
    int len   = end - start;
    int chunk = (len + SPLIT2 - 1) / SPLIT2;
    int s0  = start + zs * chunk;
    int s1e = min(s0 + chunk, end);
    float s1a = 0.f, s1b = 0.f, s2a = 0.f, s2b = 0.f;
    int m = s0 + w;
    for (; m + 8 < s1e; m += 16) {
        float2 v0 = uphf(g_h2h[(size_t)m * 32 + lane]);
        float2 v1 = uphf(g_h2h[(size_t)(m + 8) * 32 + lane]);
        s1a += v0.x + v1.x; s2a += v0.x * v0.x + v1.x * v1.x;
        s1b += v0.y + v1.y; s2b += v0.y * v0.y + v1.y * v1.y;
    }
    if (m < s1e) {
        float2 v = uphf(g_h2h[(size_t)m * 32 + lane]);
        s1a += v.x; s2a += v.x * v.x;
        s1b += v.y; s2b += v.y * v.y;
    }
    __shared__ float a1[8][32][2], a2[8][32][2];
    a1[w][lane][0] = s1a; a1[w][lane][1] = s1b;
    a2[w][lane][0] = s2a; a2[w][lane][1] = s2b;
    __syncthreads();
    if (w == 0) {
#pragma unroll
        for (int t = 1; t < 8; t++) {
            s1a += a1[t][lane][0]; s1b += a1[t][lane][1];
            s2a += a2[t][lane][0]; s2b += a2[t][lane][1];
        }
        int ch2 = lane * 2;
        atomicAdd(&g_acc[65536 + g * 64 + ch2],     s1a);
        atomicAdd(&g_acc[65536 + g * 64 + ch2 + 1], s1b);
        atomicAdd(&g_acc[73728 + g * 64 + ch2],     s2a);
        atomicAdd(&g_acc[73728 + g * 64 + ch2 + 1], s2b);
    }
}

// ---------------- K8: finalize mean2/rstd2 --------------------------------------
__global__ void k_fin2() {
    int g = blockIdx.x, ch = threadIdx.x;      // 128 x 64
    int cnti = g_off[g + 1] - g_off[g]; if (cnti < 1) cnti = 1;
    float inv = 1.f / (float)cnti;
    float mean = g_acc[65536 + g * 64 + ch] * inv;
    float var  = fmaxf(g_acc[73728 + g * 64 + ch] * inv - mean * mean, 0.f);
    g_mean2[g * 64 + ch] = mean;
    g_rstd2[g * 64 + ch] = rsqrtf(var + EPS);
}

// ---------------- K9: out[perm[m]] = relu(norm2(h2)) . W3 + b3 -----------------
__global__ void k_final(const float* __restrict__ W3,
                        const float* __restrict__ b3,
                        float* __restrict__ out, int E) {
    __shared__ __align__(16) float sm[128 * 65];
    __shared__ float w3s[64];
    __shared__ int   sS[128];
    int tid = threadIdx.x;   // 128
    int m0  = blockIdx.x * 128;
    if (tid < 64) w3s[tid] = W3[tid];
    {
        int m = m0 + tid; if (m >= E) m = E - 1;
        sS[tid] = g_segS[m];
    }
    __syncthreads();
#pragma unroll
    for (int t = tid; t < 128 * 8; t += 128) {
        int rr = t >> 3, q = t & 7;          // q: 4 u32 = 8 channels
        int m = m0 + rr; if (m >= E) m = E - 1;
        uint4 v4 = __ldcs((const uint4*)&g_h2h[(size_t)m * 32 + q * 4]);
        float2 va = uphf(v4.x), vb = uphf(v4.y), vc = uphf(v4.z), vd = uphf(v4.w);
        int s = sS[rr];
        float4 mu0 = *(const float4*)&g_mean2[s * 64 + q * 8];
        float4 rs0 = *(const float4*)&g_rstd2[s * 64 + q * 8];
        float4 mu1 = *(const float4*)&g_mean2[s * 64 + q * 8 + 4];
        float4 rs1 = *(const float4*)&g_rstd2[s * 64 + q * 8 + 4];
        float* d = &sm[rr * 65 + q * 8];
        d[0] = fmaxf((va.x - mu0.x) * rs0.x, 0.f);
        d[1] = fmaxf((va.y - mu0.y) * rs0.y, 0.f);
        d[2] = fmaxf((vb.x - mu0.z) * rs0.z, 0.f);
        d[3] = fmaxf((vb.y - mu0.w) * rs0.w, 0.f);
        d[4] = fmaxf((vc.x - mu1.x) * rs1.x, 0.f);
        d[5] = fmaxf((vc.y - mu1.y) * rs1.y, 0.f);
        d[6] = fmaxf((vd.x - mu1.z) * rs1.z, 0.f);
        d[7] = fmaxf((vd.y - mu1.w) * rs1.w, 0.f);
    }
    __syncthreads();
    int m = m0 + tid;
    if (m < E) {
        float acc = 0.f;
#pragma unroll
        for (int k = 0; k < 64; k++) acc += sm[tid * 65 + k] * w3s[k];
        out[g_perm[m]] = acc + b3[0];
    }
}

// ---------------- launch ---------------------------------------------------------
extern "C" void kernel_launch(void* const* d_in, const int* in_sizes, int n_in,
                              void* d_out, int out_size) {
    const float* emb = (const float*)d_in[0];
    const void*  ei  = d_in[1];
    const void*  bt  = d_in[2];
    const float* W1  = (const float*)d_in[3];
    // d_in[4] = b1 : cancels exactly through affine-free InstanceNorm
    const float* W2  = (const float*)d_in[5];
    // d_in[6] = b2 : cancels exactly through affine-free InstanceNorm
    const float* W3  = (const float*)d_in[7];
    const float* b3  = (const float*)d_in[8];
    float* out = (float*)d_out;

    int Nn = in_sizes[0] / 64;
    int E  = in_sizes[1] / 2;

    int nEdgeBlk = (E + 255) / 256;
    int nPqBlk   = ((Nn + 127) / 128) * 8;

    k_prep<<<176 + nEdgeBlk, 256>>>(ei, W1, W2, E, Nn);          // 1
    k_scan_node<<<1, 1024>>>(bt, E, Nn);                         // 2
    k_sp<<<nEdgeBlk + nPqBlk, 256>>>(bt, emb, E, Nn, nEdgeBlk);  // 3
    k_stats1a<<<dim3(128, SPLIT1), 256>>>();                     // 4 (profiled)
    k_fin1<<<128, 256>>>();                                      // 5
    k_gemm2<<<(E + 127) / 128, 256>>>(E);                        // 6
    k_stats2a<<<dim3(128, SPLIT2), 256>>>();                     // 7
    k_fin2<<<128, 64>>>();                                       // 8
    k_final<<<(E + 127) / 128, 128>>>(W3, b3, out, E);           // 9
}